// round 5
// baseline (speedup 1.0000x reference)
#include <cuda_runtime.h>
#include <math.h>

#define NMAX 100000
#define EMAX 1600000
#define HID 64
#define NGRAPHS 64
#define JKDIM 192
#define SCAN_BLK 1024
#define MAX_SCAN_BLOCKS 128

// ---------------- scratch (device globals: no allocation allowed) ----------
__device__ int   g_deg[NMAX];
__device__ int   g_rowptr[NMAX + 1];
__device__ int   g_cursor[NMAX];
__device__ int   g_scanloc[NMAX];
__device__ int   g_blocksum[MAX_SCAN_BLOCKS];
__device__ int   g_blockoff[MAX_SCAN_BLOCKS];
__device__ int   g_csr_src[EMAX];
__device__ float g_dinv[NMAX];
__device__ float g_ys[(size_t)NMAX * HID];   // UNSCALED  A@W
__device__ float g_h [(size_t)NMAX * HID];
__device__ float g_pooled[NGRAPHS * JKDIM];
__device__ float g_cnt[NGRAPHS];

// ---------------- f32x2 helpers ---------------------------------------------
__device__ __forceinline__ unsigned long long pack2(float lo, float hi) {
    unsigned long long r;
    asm("mov.b64 %0, {%1, %2};" : "=l"(r) : "f"(lo), "f"(hi));
    return r;
}
__device__ __forceinline__ void unpack2(unsigned long long v, float& lo, float& hi) {
    asm("mov.b64 {%0, %1}, %2;" : "=f"(lo), "=f"(hi) : "l"(v));
}
__device__ __forceinline__ void fma2(unsigned long long& d, unsigned long long a,
                                     unsigned long long b) {
    asm("fma.rn.f32x2 %0, %1, %2, %0;" : "+l"(d) : "l"(a), "l"(b));
}

// ---------------- init ------------------------------------------------------
__global__ void zero_kernel(int N) {
    int i = blockIdx.x * blockDim.x + threadIdx.x;
    if (i < N) g_deg[i] = 0;
    if (i < NGRAPHS * JKDIM) g_pooled[i] = 0.f;
    if (i < NGRAPHS) g_cnt[i] = 0.f;
}

__global__ void degree_kernel(const int* __restrict__ ei, int E) {
    int e = blockIdx.x * blockDim.x + threadIdx.x;
    if (e < E) atomicAdd(&g_deg[ei[E + e]], 1);
}

// ---------------- scan (also computes dinv) ----------------------------------
__global__ __launch_bounds__(SCAN_BLK) void block_scan_kernel(int N) {
    __shared__ int bs[SCAN_BLK];
    int t = threadIdx.x;
    int i = blockIdx.x * SCAN_BLK + t;
    int v = (i < N) ? g_deg[i] : 0;
    if (i < N) g_dinv[i] = rsqrtf((float)(v + 1));  // +1 self loop
    bs[t] = v;
    __syncthreads();
#pragma unroll
    for (int off = 1; off < SCAN_BLK; off <<= 1) {
        int u = (t >= off) ? bs[t - off] : 0;
        __syncthreads();
        bs[t] += u;
        __syncthreads();
    }
    if (i < N) g_scanloc[i] = bs[t] - v;
    if (t == SCAN_BLK - 1) g_blocksum[blockIdx.x] = bs[t];
}

__global__ void scan_blocksums_kernel(int nb) {
    __shared__ int bs[MAX_SCAN_BLOCKS];
    int t = threadIdx.x;
    int v = (t < nb) ? g_blocksum[t] : 0;
    bs[t] = v;
    __syncthreads();
#pragma unroll
    for (int off = 1; off < MAX_SCAN_BLOCKS; off <<= 1) {
        int u = (t >= off) ? bs[t - off] : 0;
        __syncthreads();
        bs[t] += u;
        __syncthreads();
    }
    if (t < nb) g_blockoff[t] = bs[t] - v;
}

__global__ void apply_offsets_kernel(int N, int E) {
    int i = blockIdx.x * blockDim.x + threadIdx.x;
    if (i < N) {
        int r = g_scanloc[i] + g_blockoff[i / SCAN_BLK];
        g_rowptr[i] = r;
        g_cursor[i] = r;
    }
    if (i == 0) g_rowptr[N] = E;
}

__global__ void fill_kernel(const int* __restrict__ ei, int E) {
    int e = blockIdx.x * blockDim.x + threadIdx.x;
    if (e < E) {
        int d = ei[E + e];
        int pos = atomicAdd(&g_cursor[d], 1);
        g_csr_src[pos] = ei[e];
    }
}

// ---------------- GEMM: ys = A @ W  (unscaled), f32x2 inner loop -------------
template <int KTOT>
__global__ __launch_bounds__(256) void gemm_kernel(const float* __restrict__ A,
                                                   const float* __restrict__ W,
                                                   int N) {
    __shared__ float Ask[32][132];
    __shared__ float Ws[32][64];

    const float* __restrict__ Ap = A ? A : g_h;

    int tid = threadIdx.x;
    int tx = tid & 15;
    int ty = tid >> 4;
    int rowBase = blockIdx.x * 128;

    unsigned long long acc2[4][4];
#pragma unroll
    for (int i = 0; i < 4; i++)
#pragma unroll
        for (int j = 0; j < 4; j++) acc2[i][j] = 0ULL;

    for (int kc = 0; kc < KTOT; kc += 32) {
        {
            int k8 = tid & 7;
            int r0 = tid >> 3;
#pragma unroll
            for (int p = 0; p < 4; p++) {
                int r = r0 + p * 32;
                int grow = rowBase + r;
                float4 v = make_float4(0.f, 0.f, 0.f, 0.f);
                if (grow < N)
                    v = *(const float4*)(Ap + (size_t)grow * KTOT + kc + k8 * 4);
                Ask[k8 * 4 + 0][r] = v.x;
                Ask[k8 * 4 + 1][r] = v.y;
                Ask[k8 * 4 + 2][r] = v.z;
                Ask[k8 * 4 + 3][r] = v.w;
            }
        }
        {
            int c4 = tid & 15;
            int kr = tid >> 4;
#pragma unroll
            for (int p = 0; p < 2; p++) {
                int k = kr + p * 16;
                *(float4*)&Ws[k][c4 * 4] =
                    *(const float4*)(W + (size_t)(kc + k) * 64 + c4 * 4);
            }
        }
        __syncthreads();
#pragma unroll
        for (int kk = 0; kk < 32; kk++) {
            float4 w = *(const float4*)&Ws[kk][tx * 4];
            float4 a0 = *(const float4*)&Ask[kk][ty * 8];
            float4 a1 = *(const float4*)&Ask[kk][ty * 8 + 4];

            unsigned long long w2[4];
            w2[0] = pack2(w.x, w.x);
            w2[1] = pack2(w.y, w.y);
            w2[2] = pack2(w.z, w.z);
            w2[3] = pack2(w.w, w.w);

            unsigned long long a2[4];
            a2[0] = pack2(a0.x, a0.y);
            a2[1] = pack2(a0.z, a0.w);
            a2[2] = pack2(a1.x, a1.y);
            a2[3] = pack2(a1.z, a1.w);

#pragma unroll
            for (int i = 0; i < 4; i++)
#pragma unroll
                for (int j = 0; j < 4; j++) fma2(acc2[i][j], a2[i], w2[j]);
        }
        __syncthreads();
    }

#pragma unroll
    for (int i2 = 0; i2 < 4; i2++) {
#pragma unroll
        for (int sub = 0; sub < 2; sub++) {
            int row = rowBase + ty * 8 + i2 * 2 + sub;
            if (row < N) {
                float4 v;
                float lo, hi;
                unpack2(acc2[i2][0], lo, hi); v.x = (sub ? hi : lo);
                unpack2(acc2[i2][1], lo, hi); v.y = (sub ? hi : lo);
                unpack2(acc2[i2][2], lo, hi); v.z = (sub ? hi : lo);
                unpack2(acc2[i2][3], lo, hi); v.w = (sub ? hi : lo);
                *(float4*)(g_ys + (size_t)row * HID + tx * 4) = v;
            }
        }
    }
}

// ---- aggregation (pull) + fused pooling ------------------------------------
// h[n] = relu(dinv[n]*(dinv[n]*ys[n] + sum dinv[s]*ys[s]) + b)
__global__ __launch_bounds__(256) void aggregate_kernel(
    const float* __restrict__ bias, const int* __restrict__ batch,
    int off, int doPool, int doCount, int N) {
    int gid = blockIdx.x * blockDim.x + threadIdx.x;
    int node = gid >> 4;
    int f4 = (gid & 15) * 4;
    bool valid = node < N;

    float4 h = make_float4(0.f, 0.f, 0.f, 0.f);
    if (valid) {
        int beg = __ldg(&g_rowptr[node]);
        int end = __ldg(&g_rowptr[node + 1]);
        float dvn = __ldg(&g_dinv[node]);

        float4 sf = *(const float4*)(g_ys + (size_t)node * HID + f4);  // self
        float4 s0, s1, s2, s3;
        s0.x = sf.x * dvn; s0.y = sf.y * dvn; s0.z = sf.z * dvn; s0.w = sf.w * dvn;
        s1 = make_float4(0.f, 0.f, 0.f, 0.f);
        s2 = make_float4(0.f, 0.f, 0.f, 0.f);
        s3 = make_float4(0.f, 0.f, 0.f, 0.f);

        int e = beg;
        for (; e + 4 <= end; e += 4) {
            int a = __ldg(&g_csr_src[e]);
            int b = __ldg(&g_csr_src[e + 1]);
            int c = __ldg(&g_csr_src[e + 2]);
            int d = __ldg(&g_csr_src[e + 3]);
            float da = __ldg(&g_dinv[a]);
            float db = __ldg(&g_dinv[b]);
            float dc = __ldg(&g_dinv[c]);
            float dd = __ldg(&g_dinv[d]);
            float4 v0 = *(const float4*)(g_ys + (size_t)a * HID + f4);
            float4 v1 = *(const float4*)(g_ys + (size_t)b * HID + f4);
            float4 v2 = *(const float4*)(g_ys + (size_t)c * HID + f4);
            float4 v3 = *(const float4*)(g_ys + (size_t)d * HID + f4);
            s0.x += v0.x * da; s0.y += v0.y * da; s0.z += v0.z * da; s0.w += v0.w * da;
            s1.x += v1.x * db; s1.y += v1.y * db; s1.z += v1.z * db; s1.w += v1.w * db;
            s2.x += v2.x * dc; s2.y += v2.y * dc; s2.z += v2.z * dc; s2.w += v2.w * dc;
            s3.x += v3.x * dd; s3.y += v3.y * dd; s3.z += v3.z * dd; s3.w += v3.w * dd;
        }
        for (; e < end; e++) {
            int a = __ldg(&g_csr_src[e]);
            float da = __ldg(&g_dinv[a]);
            float4 v = *(const float4*)(g_ys + (size_t)a * HID + f4);
            s0.x += v.x * da; s0.y += v.y * da; s0.z += v.z * da; s0.w += v.w * da;
        }
        s0.x += s1.x + s2.x + s3.x;
        s0.y += s1.y + s2.y + s3.y;
        s0.z += s1.z + s2.z + s3.z;
        s0.w += s1.w + s2.w + s3.w;

        float4 b4 = *(const float4*)(bias + f4);
        h.x = fmaxf(s0.x * dvn + b4.x, 0.f);
        h.y = fmaxf(s0.y * dvn + b4.y, 0.f);
        h.z = fmaxf(s0.z * dvn + b4.z, 0.f);
        h.w = fmaxf(s0.w * dvn + b4.w, 0.f);
        *(float4*)(g_h + (size_t)node * HID + f4) = h;
    }

    if (doPool) {
        __shared__ float sh[16][64];
        __shared__ int sg[16];
        int nl = threadIdx.x >> 4;
        int f4i = threadIdx.x & 15;
        *(float4*)&sh[nl][f4i * 4] = h;
        if (f4i == 0) sg[nl] = valid ? __ldg(&batch[node]) : -1;
        __syncthreads();

        if (threadIdx.x < 64) {
            int gmin = 0x7fffffff, gmax = -1;
#pragma unroll
            for (int i = 0; i < 16; i++) {
                int g = sg[i];
                if (g >= 0) { gmin = min(gmin, g); gmax = max(gmax, g); }
            }
            for (int g = gmin; g <= gmax; g++) {
                float s = 0.f;
                int cnt = 0;
#pragma unroll
                for (int i = 0; i < 16; i++)
                    if (sg[i] == g) { s += sh[i][threadIdx.x]; cnt++; }
                atomicAdd(&g_pooled[g * JKDIM + off + threadIdx.x], s);
                if (doCount && threadIdx.x == 0) atomicAdd(&g_cnt[g], (float)cnt);
            }
        }
    }
}

// ---------------- head: mean-pool normalize + linear + log_softmax ----------
__global__ void head_kernel(const float* __restrict__ Wl,
                            const float* __restrict__ bl,
                            float* __restrict__ out) {
    int g = threadIdx.x;
    if (g >= NGRAPHS) return;
    float ic = 1.f / fmaxf(g_cnt[g], 1.f);
    float logit[10];
#pragma unroll
    for (int j = 0; j < 10; j++) logit[j] = bl[j];
    for (int k = 0; k < JKDIM; k++) {
        float v = g_pooled[g * JKDIM + k] * ic;
#pragma unroll
        for (int j = 0; j < 10; j++) logit[j] += v * Wl[k * 10 + j];
    }
    float m = logit[0];
#pragma unroll
    for (int j = 1; j < 10; j++) m = fmaxf(m, logit[j]);
    float s = 0.f;
#pragma unroll
    for (int j = 0; j < 10; j++) s += expf(logit[j] - m);
    float lse = logf(s);
#pragma unroll
    for (int j = 0; j < 10; j++) out[g * 10 + j] = logit[j] - m - lse;
}

// ---------------- launch -----------------------------------------------------
extern "C" void kernel_launch(void* const* d_in, const int* in_sizes, int n_in,
                              void* d_out, int out_size) {
    const float* x  = (const float*)d_in[0];
    const float* W1 = (const float*)d_in[1];
    const float* b1 = (const float*)d_in[2];
    const float* W2 = (const float*)d_in[3];
    const float* b2 = (const float*)d_in[4];
    const float* W3 = (const float*)d_in[5];
    const float* b3 = (const float*)d_in[6];
    const float* W4 = (const float*)d_in[7];
    const float* b4 = (const float*)d_in[8];
    const float* Wl = (const float*)d_in[9];
    const float* bl = (const float*)d_in[10];
    const int* ei    = (const int*)d_in[11];
    const int* batch = (const int*)d_in[12];
    float* out = (float*)d_out;

    int N = in_sizes[12];
    int E = in_sizes[11] / 2;

    int threads = 256;
    int gridN = (N + threads - 1) / threads;
    int gridE = (E + threads - 1) / threads;
    int gemmGrid = (N + 127) / 128;
    int aggGrid = (N * 16 + threads - 1) / threads;
    int nScanBlocks = (N + SCAN_BLK - 1) / SCAN_BLK;

    // one-time host-side stream/event resources (no device memory involved)
    static cudaStream_t s2 = nullptr;
    static cudaEvent_t evFork = nullptr, evJoin = nullptr;
    if (!s2) {
        cudaStreamCreateWithFlags(&s2, cudaStreamNonBlocking);
        cudaEventCreateWithFlags(&evFork, cudaEventDisableTiming);
        cudaEventCreateWithFlags(&evJoin, cudaEventDisableTiming);
    }

    // ---- fork: gemm1 (independent of CSR build) on s2 ----
    cudaEventRecord(evFork, 0);
    cudaStreamWaitEvent(s2, evFork, 0);
    gemm_kernel<128><<<gemmGrid, 256, 0, s2>>>(x, W1, N);
    cudaEventRecord(evJoin, s2);

    // ---- CSR build chain on the main stream ----
    zero_kernel<<<gridN, threads>>>(N);
    degree_kernel<<<gridE, threads>>>(ei, E);
    block_scan_kernel<<<nScanBlocks, SCAN_BLK>>>(N);
    scan_blocksums_kernel<<<1, MAX_SCAN_BLOCKS>>>(nScanBlocks);
    apply_offsets_kernel<<<gridN, threads>>>(N, E);
    fill_kernel<<<gridE, threads>>>(ei, E);

    // ---- join ----
    cudaStreamWaitEvent(0, evJoin, 0);

    // layer 1: pool x1 -> [0:64), also counts
    aggregate_kernel<<<aggGrid, threads>>>(b1, batch, 0, 1, 1, N);

    // layer 2; pool x2 -> [64:128)
    gemm_kernel<64><<<gemmGrid, 256>>>(nullptr, W2, N);
    aggregate_kernel<<<aggGrid, threads>>>(b2, batch, 64, 1, 0, N);

    // layer 3 (no pool)
    gemm_kernel<64><<<gemmGrid, 256>>>(nullptr, W3, N);
    aggregate_kernel<<<aggGrid, threads>>>(b3, batch, 0, 0, 0, N);

    // layer 4 (overwrites x3, as in reference); pool -> [128:192)
    gemm_kernel<64><<<gemmGrid, 256>>>(nullptr, W4, N);
    aggregate_kernel<<<aggGrid, threads>>>(b4, batch, 128, 1, 0, N);

    head_kernel<<<1, 64>>>(Wl, bl, out);
}

// round 6
// speedup vs baseline: 1.0145x; 1.0145x over previous
#include <cuda_runtime.h>
#include <cuda_fp16.h>
#include <math.h>

#define NMAX 100000
#define EMAX 1600000
#define HID 64
#define NGRAPHS 64
#define JKDIM 192
#define SCAN_BLK 1024
#define MAX_SCAN_BLOCKS 128

// ---------------- scratch (device globals: no allocation allowed) ----------
__device__ int    g_deg[NMAX];
__device__ int    g_rowptr[NMAX + 1];
__device__ int    g_cursor[NMAX];
__device__ int    g_scanloc[NMAX];
__device__ int    g_blocksum[MAX_SCAN_BLOCKS];
__device__ int    g_blockoff[MAX_SCAN_BLOCKS];
__device__ int    g_csr_src[EMAX];
__device__ float  g_dinv[NMAX];
__device__ __half g_ysh[(size_t)NMAX * HID];  // dinv-scaled A@W, fp16
__device__ float  g_h [(size_t)NMAX * HID];
__device__ float  g_pooled[NGRAPHS * JKDIM];
__device__ float  g_cnt[NGRAPHS];

// ---------------- f32x2 helpers ---------------------------------------------
__device__ __forceinline__ unsigned long long pack2(float lo, float hi) {
    unsigned long long r;
    asm("mov.b64 %0, {%1, %2};" : "=l"(r) : "f"(lo), "f"(hi));
    return r;
}
__device__ __forceinline__ void unpack2(unsigned long long v, float& lo, float& hi) {
    asm("mov.b64 {%0, %1}, %2;" : "=f"(lo), "=f"(hi) : "l"(v));
}
__device__ __forceinline__ void fma2(unsigned long long& d, unsigned long long a,
                                     unsigned long long b) {
    asm("fma.rn.f32x2 %0, %1, %2, %0;" : "+l"(d) : "l"(a), "l"(b));
}

// ---------------- init ------------------------------------------------------
__global__ void zero_kernel(int N) {
    int i = blockIdx.x * blockDim.x + threadIdx.x;
    if (i < N) g_deg[i] = 0;
    if (i < NGRAPHS * JKDIM) g_pooled[i] = 0.f;
    if (i < NGRAPHS) g_cnt[i] = 0.f;
}

__global__ void degree_kernel(const int* __restrict__ ei, int E) {
    int e = blockIdx.x * blockDim.x + threadIdx.x;
    if (e < E) atomicAdd(&g_deg[ei[E + e]], 1);
}

// ---------------- scan (also computes dinv) ----------------------------------
__global__ __launch_bounds__(SCAN_BLK) void block_scan_kernel(int N) {
    __shared__ int bs[SCAN_BLK];
    int t = threadIdx.x;
    int i = blockIdx.x * SCAN_BLK + t;
    int v = (i < N) ? g_deg[i] : 0;
    if (i < N) g_dinv[i] = rsqrtf((float)(v + 1));  // +1 self loop
    bs[t] = v;
    __syncthreads();
#pragma unroll
    for (int off = 1; off < SCAN_BLK; off <<= 1) {
        int u = (t >= off) ? bs[t - off] : 0;
        __syncthreads();
        bs[t] += u;
        __syncthreads();
    }
    if (i < N) g_scanloc[i] = bs[t] - v;
    if (t == SCAN_BLK - 1) g_blocksum[blockIdx.x] = bs[t];
}

__global__ void scan_blocksums_kernel(int nb) {
    __shared__ int bs[MAX_SCAN_BLOCKS];
    int t = threadIdx.x;
    int v = (t < nb) ? g_blocksum[t] : 0;
    bs[t] = v;
    __syncthreads();
#pragma unroll
    for (int off = 1; off < MAX_SCAN_BLOCKS; off <<= 1) {
        int u = (t >= off) ? bs[t - off] : 0;
        __syncthreads();
        bs[t] += u;
        __syncthreads();
    }
    if (t < nb) g_blockoff[t] = bs[t] - v;
}

__global__ void apply_offsets_kernel(int N, int E) {
    int i = blockIdx.x * blockDim.x + threadIdx.x;
    if (i < N) {
        int r = g_scanloc[i] + g_blockoff[i / SCAN_BLK];
        g_rowptr[i] = r;
        g_cursor[i] = r;
    }
    if (i == 0) g_rowptr[N] = E;
}

__global__ void fill_kernel(const int* __restrict__ ei, int E) {
    int e = blockIdx.x * blockDim.x + threadIdx.x;
    if (e < E) {
        int d = ei[E + e];
        int pos = atomicAdd(&g_cursor[d], 1);
        g_csr_src[pos] = ei[e];
    }
}

// -------- GEMM: ysh = fp16((A @ W) * dinv[row]), f32x2 inner loop -----------
template <int KTOT>
__global__ __launch_bounds__(256) void gemm_kernel(const float* __restrict__ A,
                                                   const float* __restrict__ W,
                                                   int N) {
    __shared__ float Ask[32][132];
    __shared__ float Ws[32][64];

    const float* __restrict__ Ap = A ? A : g_h;

    int tid = threadIdx.x;
    int tx = tid & 15;
    int ty = tid >> 4;
    int rowBase = blockIdx.x * 128;

    unsigned long long acc2[4][4];
#pragma unroll
    for (int i = 0; i < 4; i++)
#pragma unroll
        for (int j = 0; j < 4; j++) acc2[i][j] = 0ULL;

    for (int kc = 0; kc < KTOT; kc += 32) {
        {
            int k8 = tid & 7;
            int r0 = tid >> 3;
#pragma unroll
            for (int p = 0; p < 4; p++) {
                int r = r0 + p * 32;
                int grow = rowBase + r;
                float4 v = make_float4(0.f, 0.f, 0.f, 0.f);
                if (grow < N)
                    v = *(const float4*)(Ap + (size_t)grow * KTOT + kc + k8 * 4);
                Ask[k8 * 4 + 0][r] = v.x;
                Ask[k8 * 4 + 1][r] = v.y;
                Ask[k8 * 4 + 2][r] = v.z;
                Ask[k8 * 4 + 3][r] = v.w;
            }
        }
        {
            int c4 = tid & 15;
            int kr = tid >> 4;
#pragma unroll
            for (int p = 0; p < 2; p++) {
                int k = kr + p * 16;
                *(float4*)&Ws[k][c4 * 4] =
                    *(const float4*)(W + (size_t)(kc + k) * 64 + c4 * 4);
            }
        }
        __syncthreads();
#pragma unroll
        for (int kk = 0; kk < 32; kk++) {
            float4 w = *(const float4*)&Ws[kk][tx * 4];
            float4 a0 = *(const float4*)&Ask[kk][ty * 8];
            float4 a1 = *(const float4*)&Ask[kk][ty * 8 + 4];

            unsigned long long w2[4];
            w2[0] = pack2(w.x, w.x);
            w2[1] = pack2(w.y, w.y);
            w2[2] = pack2(w.z, w.z);
            w2[3] = pack2(w.w, w.w);

            unsigned long long a2[4];
            a2[0] = pack2(a0.x, a0.y);
            a2[1] = pack2(a0.z, a0.w);
            a2[2] = pack2(a1.x, a1.y);
            a2[3] = pack2(a1.z, a1.w);

#pragma unroll
            for (int i = 0; i < 4; i++)
#pragma unroll
                for (int j = 0; j < 4; j++) fma2(acc2[i][j], a2[i], w2[j]);
        }
        __syncthreads();
    }

#pragma unroll
    for (int i2 = 0; i2 < 4; i2++) {
#pragma unroll
        for (int sub = 0; sub < 2; sub++) {
            int row = rowBase + ty * 8 + i2 * 2 + sub;
            if (row < N) {
                float dv = g_dinv[row];
                float lo, hi;
                float4 v;
                unpack2(acc2[i2][0], lo, hi); v.x = (sub ? hi : lo) * dv;
                unpack2(acc2[i2][1], lo, hi); v.y = (sub ? hi : lo) * dv;
                unpack2(acc2[i2][2], lo, hi); v.z = (sub ? hi : lo) * dv;
                unpack2(acc2[i2][3], lo, hi); v.w = (sub ? hi : lo) * dv;
                __half2 p0 = __floats2half2_rn(v.x, v.y);
                __half2 p1 = __floats2half2_rn(v.z, v.w);
                uint2 st;
                st.x = *(unsigned int*)&p0;
                st.y = *(unsigned int*)&p1;
                *(uint2*)(g_ysh + (size_t)row * HID + tx * 4) = st;
            }
        }
    }
}

// ---- aggregation (pull, fp16 gather) + fused pooling -----------------------
// h[n] = relu(dinv[n]*(ysh[n] + sum ysh[src]) + b)
// thread layout: 8 slices per node, 8 features (4 half2) per slice.
__device__ __forceinline__ void add_h8(float* acc, uint4 v) {
    __half2* h = (__half2*)&v;
#pragma unroll
    for (int i = 0; i < 4; i++) {
        float2 f = __half22float2(h[i]);
        acc[2 * i] += f.x;
        acc[2 * i + 1] += f.y;
    }
}

__global__ __launch_bounds__(256) void aggregate_kernel(
    const float* __restrict__ bias, const int* __restrict__ batch,
    int off, int doPool, int doCount, int N) {
    int gid = blockIdx.x * blockDim.x + threadIdx.x;
    int node = gid >> 3;
    int sl = gid & 7;
    bool valid = node < N;

    const uint4* __restrict__ ysv = (const uint4*)g_ysh;  // 8 uint4 per row

    float h[8];
#pragma unroll
    for (int i = 0; i < 8; i++) h[i] = 0.f;

    if (valid) {
        int beg = __ldg(&g_rowptr[node]);
        int end = __ldg(&g_rowptr[node + 1]);
        float dvn = __ldg(&g_dinv[node]);

        float s0[8], s1[8], s2[8], s3[8];
#pragma unroll
        for (int i = 0; i < 8; i++) { s0[i] = 0.f; s1[i] = 0.f; s2[i] = 0.f; s3[i] = 0.f; }
        add_h8(s0, __ldg(&ysv[(size_t)node * 8 + sl]));  // self loop

        int e = beg;
        for (; e + 4 <= end; e += 4) {
            int a = __ldg(&g_csr_src[e]);
            int b = __ldg(&g_csr_src[e + 1]);
            int c = __ldg(&g_csr_src[e + 2]);
            int d = __ldg(&g_csr_src[e + 3]);
            uint4 v0 = __ldg(&ysv[(size_t)a * 8 + sl]);
            uint4 v1 = __ldg(&ysv[(size_t)b * 8 + sl]);
            uint4 v2 = __ldg(&ysv[(size_t)c * 8 + sl]);
            uint4 v3 = __ldg(&ysv[(size_t)d * 8 + sl]);
            add_h8(s0, v0);
            add_h8(s1, v1);
            add_h8(s2, v2);
            add_h8(s3, v3);
        }
        for (; e < end; e++) {
            int a = __ldg(&g_csr_src[e]);
            add_h8(s0, __ldg(&ysv[(size_t)a * 8 + sl]));
        }

        float4 b0 = *(const float4*)(bias + sl * 8);
        float4 b1 = *(const float4*)(bias + sl * 8 + 4);
        float bb[8] = {b0.x, b0.y, b0.z, b0.w, b1.x, b1.y, b1.z, b1.w};
#pragma unroll
        for (int i = 0; i < 8; i++) {
            float s = s0[i] + s1[i] + s2[i] + s3[i];
            h[i] = fmaxf(s * dvn + bb[i], 0.f);
        }
        float* hp = g_h + (size_t)node * HID + sl * 8;
        *(float4*)hp       = make_float4(h[0], h[1], h[2], h[3]);
        *(float4*)(hp + 4) = make_float4(h[4], h[5], h[6], h[7]);
    }

    if (doPool) {
        __shared__ float sh[32][64];
        __shared__ int sg[32];
        int nl = threadIdx.x >> 3;
        int sli = threadIdx.x & 7;
        *(float4*)&sh[nl][sli * 8]     = make_float4(h[0], h[1], h[2], h[3]);
        *(float4*)&sh[nl][sli * 8 + 4] = make_float4(h[4], h[5], h[6], h[7]);
        if (sli == 0) sg[nl] = valid ? __ldg(&batch[node]) : -1;
        __syncthreads();

        if (threadIdx.x < 64) {
            int gmin = 0x7fffffff, gmax = -1;
#pragma unroll
            for (int i = 0; i < 32; i++) {
                int g = sg[i];
                if (g >= 0) { gmin = min(gmin, g); gmax = max(gmax, g); }
            }
            for (int g = gmin; g <= gmax; g++) {
                float s = 0.f;
                int cnt = 0;
#pragma unroll
                for (int i = 0; i < 32; i++)
                    if (sg[i] == g) { s += sh[i][threadIdx.x]; cnt++; }
                atomicAdd(&g_pooled[g * JKDIM + off + threadIdx.x], s);
                if (doCount && threadIdx.x == 0) atomicAdd(&g_cnt[g], (float)cnt);
            }
        }
    }
}

// ---------------- head: mean-pool normalize + linear + log_softmax ----------
__global__ void head_kernel(const float* __restrict__ Wl,
                            const float* __restrict__ bl,
                            float* __restrict__ out) {
    int g = threadIdx.x;
    if (g >= NGRAPHS) return;
    float ic = 1.f / fmaxf(g_cnt[g], 1.f);
    float logit[10];
#pragma unroll
    for (int j = 0; j < 10; j++) logit[j] = bl[j];
    for (int k = 0; k < JKDIM; k++) {
        float v = g_pooled[g * JKDIM + k] * ic;
#pragma unroll
        for (int j = 0; j < 10; j++) logit[j] += v * Wl[k * 10 + j];
    }
    float m = logit[0];
#pragma unroll
    for (int j = 1; j < 10; j++) m = fmaxf(m, logit[j]);
    float s = 0.f;
#pragma unroll
    for (int j = 0; j < 10; j++) s += expf(logit[j] - m);
    float lse = logf(s);
#pragma unroll
    for (int j = 0; j < 10; j++) out[g * 10 + j] = logit[j] - m - lse;
}

// ---------------- launch -----------------------------------------------------
extern "C" void kernel_launch(void* const* d_in, const int* in_sizes, int n_in,
                              void* d_out, int out_size) {
    const float* x  = (const float*)d_in[0];
    const float* W1 = (const float*)d_in[1];
    const float* b1 = (const float*)d_in[2];
    const float* W2 = (const float*)d_in[3];
    const float* b2 = (const float*)d_in[4];
    const float* W3 = (const float*)d_in[5];
    const float* b3 = (const float*)d_in[6];
    const float* W4 = (const float*)d_in[7];
    const float* b4 = (const float*)d_in[8];
    const float* Wl = (const float*)d_in[9];
    const float* bl = (const float*)d_in[10];
    const int* ei    = (const int*)d_in[11];
    const int* batch = (const int*)d_in[12];
    float* out = (float*)d_out;

    int N = in_sizes[12];
    int E = in_sizes[11] / 2;

    int threads = 256;
    int gridN = (N + threads - 1) / threads;
    int gridE = (E + threads - 1) / threads;
    int gemmGrid = (N + 127) / 128;
    int aggGrid = (N * 8 + threads - 1) / threads;
    int nScanBlocks = (N + SCAN_BLK - 1) / SCAN_BLK;

    zero_kernel<<<gridN, threads>>>(N);
    degree_kernel<<<gridE, threads>>>(ei, E);
    block_scan_kernel<<<nScanBlocks, SCAN_BLK>>>(N);
    scan_blocksums_kernel<<<1, MAX_SCAN_BLOCKS>>>(nScanBlocks);
    apply_offsets_kernel<<<gridN, threads>>>(N, E);
    fill_kernel<<<gridE, threads>>>(ei, E);

    // layer 1 (input x, K=128); pool x1 -> [0:64), also counts
    gemm_kernel<128><<<gemmGrid, 256>>>(x, W1, N);
    aggregate_kernel<<<aggGrid, threads>>>(b1, batch, 0, 1, 1, N);

    // layer 2; pool x2 -> [64:128)
    gemm_kernel<64><<<gemmGrid, 256>>>(nullptr, W2, N);
    aggregate_kernel<<<aggGrid, threads>>>(b2, batch, 64, 1, 0, N);

    // layer 3 (no pool)
    gemm_kernel<64><<<gemmGrid, 256>>>(nullptr, W3, N);
    aggregate_kernel<<<aggGrid, threads>>>(b3, batch, 0, 0, 0, N);

    // layer 4 (overwrites x3, as in reference); pool -> [128:192)
    gemm_kernel<64><<<gemmGrid, 256>>>(nullptr, W4, N);
    aggregate_kernel<<<aggGrid, threads>>>(b4, batch, 128, 1, 0, N);

    head_kernel<<<1, 64>>>(Wl, bl, out);
}

// round 7
// speedup vs baseline: 1.0155x; 1.0010x over previous
#include <cuda_runtime.h>
#include <cuda_fp16.h>
#include <math.h>

#define NMAX 100000
#define EMAX 1600000
#define HID 64
#define NGRAPHS 64
#define JKDIM 192
#define SCAN_BLK 1024
#define MAX_SCAN_BLOCKS 128

// ---------------- scratch (device globals: no allocation allowed) ----------
__device__ int    g_deg[NMAX];
__device__ int    g_rowptr[NMAX + 1];
__device__ int    g_cursor[NMAX];
__device__ int    g_scanloc[NMAX];
__device__ int    g_blocksum[MAX_SCAN_BLOCKS];
__device__ int    g_blockoff[MAX_SCAN_BLOCKS];
__device__ int    g_csr_src[EMAX];
__device__ float  g_dinv[NMAX];
__device__ __half g_ysh[(size_t)NMAX * HID];  // dinv-scaled A@W, fp16
__device__ float  g_h [(size_t)NMAX * HID];
__device__ float  g_pooled[NGRAPHS * JKDIM];
__device__ float  g_cnt[NGRAPHS];

// ---------------- f32x2 helpers ---------------------------------------------
__device__ __forceinline__ unsigned long long pack2(float lo, float hi) {
    unsigned long long r;
    asm("mov.b64 %0, {%1, %2};" : "=l"(r) : "f"(lo), "f"(hi));
    return r;
}
__device__ __forceinline__ void unpack2(unsigned long long v, float& lo, float& hi) {
    asm("mov.b64 {%0, %1}, %2;" : "=f"(lo), "=f"(hi) : "l"(v));
}
__device__ __forceinline__ void fma2(unsigned long long& d, unsigned long long a,
                                     unsigned long long b) {
    asm("fma.rn.f32x2 %0, %1, %2, %0;" : "+l"(d) : "l"(a), "l"(b));
}

// ---------------- init ------------------------------------------------------
__global__ void zero_kernel(int N) {
    int i = blockIdx.x * blockDim.x + threadIdx.x;
    if (i < N) g_deg[i] = 0;
    if (i < NGRAPHS * JKDIM) g_pooled[i] = 0.f;
    if (i < NGRAPHS) g_cnt[i] = 0.f;
}

__global__ void degree_kernel(const int* __restrict__ ei, int E) {
    int e = blockIdx.x * blockDim.x + threadIdx.x;
    if (e < E) atomicAdd(&g_deg[ei[E + e]], 1);
}

// ---------------- scan (also computes dinv) ----------------------------------
__global__ __launch_bounds__(SCAN_BLK) void block_scan_kernel(int N) {
    __shared__ int bs[SCAN_BLK];
    int t = threadIdx.x;
    int i = blockIdx.x * SCAN_BLK + t;
    int v = (i < N) ? g_deg[i] : 0;
    if (i < N) g_dinv[i] = rsqrtf((float)(v + 1));  // +1 self loop
    bs[t] = v;
    __syncthreads();
#pragma unroll
    for (int off = 1; off < SCAN_BLK; off <<= 1) {
        int u = (t >= off) ? bs[t - off] : 0;
        __syncthreads();
        bs[t] += u;
        __syncthreads();
    }
    if (i < N) g_scanloc[i] = bs[t] - v;
    if (t == SCAN_BLK - 1) g_blocksum[blockIdx.x] = bs[t];
}

__global__ void scan_blocksums_kernel(int nb) {
    __shared__ int bs[MAX_SCAN_BLOCKS];
    int t = threadIdx.x;
    int v = (t < nb) ? g_blocksum[t] : 0;
    bs[t] = v;
    __syncthreads();
#pragma unroll
    for (int off = 1; off < MAX_SCAN_BLOCKS; off <<= 1) {
        int u = (t >= off) ? bs[t - off] : 0;
        __syncthreads();
        bs[t] += u;
        __syncthreads();
    }
    if (t < nb) g_blockoff[t] = bs[t] - v;
}

__global__ void apply_offsets_kernel(int N, int E) {
    int i = blockIdx.x * blockDim.x + threadIdx.x;
    if (i < N) {
        int r = g_scanloc[i] + g_blockoff[i / SCAN_BLK];
        g_rowptr[i] = r;
        g_cursor[i] = r;
    }
    if (i == 0) g_rowptr[N] = E;
}

__global__ void fill_kernel(const int* __restrict__ ei, int E) {
    int e = blockIdx.x * blockDim.x + threadIdx.x;
    if (e < E) {
        int d = ei[E + e];
        int pos = atomicAdd(&g_cursor[d], 1);
        g_csr_src[pos] = ei[e];
    }
}

// -------- GEMM: ysh = fp16((A @ W) * dinv[row]), f32x2 inner loop -----------
template <int KTOT>
__global__ __launch_bounds__(256) void gemm_kernel(const float* __restrict__ A,
                                                   const float* __restrict__ W,
                                                   int N) {
    __shared__ float Ask[32][132];
    __shared__ float Ws[32][64];

    const float* __restrict__ Ap = A ? A : g_h;

    int tid = threadIdx.x;
    int tx = tid & 15;
    int ty = tid >> 4;
    int rowBase = blockIdx.x * 128;

    unsigned long long acc2[4][4];
#pragma unroll
    for (int i = 0; i < 4; i++)
#pragma unroll
        for (int j = 0; j < 4; j++) acc2[i][j] = 0ULL;

    for (int kc = 0; kc < KTOT; kc += 32) {
        {
            int k8 = tid & 7;
            int r0 = tid >> 3;
#pragma unroll
            for (int p = 0; p < 4; p++) {
                int r = r0 + p * 32;
                int grow = rowBase + r;
                float4 v = make_float4(0.f, 0.f, 0.f, 0.f);
                if (grow < N)
                    v = *(const float4*)(Ap + (size_t)grow * KTOT + kc + k8 * 4);
                Ask[k8 * 4 + 0][r] = v.x;
                Ask[k8 * 4 + 1][r] = v.y;
                Ask[k8 * 4 + 2][r] = v.z;
                Ask[k8 * 4 + 3][r] = v.w;
            }
        }
        {
            int c4 = tid & 15;
            int kr = tid >> 4;
#pragma unroll
            for (int p = 0; p < 2; p++) {
                int k = kr + p * 16;
                *(float4*)&Ws[k][c4 * 4] =
                    *(const float4*)(W + (size_t)(kc + k) * 64 + c4 * 4);
            }
        }
        __syncthreads();
#pragma unroll
        for (int kk = 0; kk < 32; kk++) {
            float4 w = *(const float4*)&Ws[kk][tx * 4];
            float4 a0 = *(const float4*)&Ask[kk][ty * 8];
            float4 a1 = *(const float4*)&Ask[kk][ty * 8 + 4];

            unsigned long long w2[4];
            w2[0] = pack2(w.x, w.x);
            w2[1] = pack2(w.y, w.y);
            w2[2] = pack2(w.z, w.z);
            w2[3] = pack2(w.w, w.w);

            unsigned long long a2[4];
            a2[0] = pack2(a0.x, a0.y);
            a2[1] = pack2(a0.z, a0.w);
            a2[2] = pack2(a1.x, a1.y);
            a2[3] = pack2(a1.z, a1.w);

#pragma unroll
            for (int i = 0; i < 4; i++)
#pragma unroll
                for (int j = 0; j < 4; j++) fma2(acc2[i][j], a2[i], w2[j]);
        }
        __syncthreads();
    }

#pragma unroll
    for (int i2 = 0; i2 < 4; i2++) {
#pragma unroll
        for (int sub = 0; sub < 2; sub++) {
            int row = rowBase + ty * 8 + i2 * 2 + sub;
            if (row < N) {
                float dv = g_dinv[row];
                float lo, hi;
                float4 v;
                unpack2(acc2[i2][0], lo, hi); v.x = (sub ? hi : lo) * dv;
                unpack2(acc2[i2][1], lo, hi); v.y = (sub ? hi : lo) * dv;
                unpack2(acc2[i2][2], lo, hi); v.z = (sub ? hi : lo) * dv;
                unpack2(acc2[i2][3], lo, hi); v.w = (sub ? hi : lo) * dv;
                __half2 p0 = __floats2half2_rn(v.x, v.y);
                __half2 p1 = __floats2half2_rn(v.z, v.w);
                uint2 st;
                st.x = *(unsigned int*)&p0;
                st.y = *(unsigned int*)&p1;
                *(uint2*)(g_ysh + (size_t)row * HID + tx * 4) = st;
            }
        }
    }
}

// ---- aggregation (pull, fp16 gather, 8-deep MLP) + fused pooling -----------
__device__ __forceinline__ void add_h8(float* acc, uint4 v) {
    __half2* h = (__half2*)&v;
#pragma unroll
    for (int i = 0; i < 4; i++) {
        float2 f = __half22float2(h[i]);
        acc[2 * i] += f.x;
        acc[2 * i + 1] += f.y;
    }
}

__global__ __launch_bounds__(256) void aggregate_kernel(
    const float* __restrict__ bias, const int* __restrict__ batch,
    int off, int doPool, int doCount, int N) {
    int gid = blockIdx.x * blockDim.x + threadIdx.x;
    int node = gid >> 3;
    int sl = gid & 7;
    bool valid = node < N;

    const uint4* __restrict__ ysv = (const uint4*)g_ysh;  // 8 uint4 per row

    float h[8];
#pragma unroll
    for (int i = 0; i < 8; i++) h[i] = 0.f;

    if (valid) {
        int beg = __ldg(&g_rowptr[node]);
        int end = __ldg(&g_rowptr[node + 1]);
        float dvn = __ldg(&g_dinv[node]);

        float s0[8], s1[8], s2[8], s3[8];
#pragma unroll
        for (int i = 0; i < 8; i++) { s0[i] = 0.f; s1[i] = 0.f; s2[i] = 0.f; s3[i] = 0.f; }
        add_h8(s0, __ldg(&ysv[(size_t)node * 8 + sl]));  // self loop

        int e = beg;
        // 8-wide: 8 independent idx loads, then 8 independent gathers in flight
        for (; e + 8 <= end; e += 8) {
            int a0 = __ldg(&g_csr_src[e]);
            int a1 = __ldg(&g_csr_src[e + 1]);
            int a2 = __ldg(&g_csr_src[e + 2]);
            int a3 = __ldg(&g_csr_src[e + 3]);
            int a4 = __ldg(&g_csr_src[e + 4]);
            int a5 = __ldg(&g_csr_src[e + 5]);
            int a6 = __ldg(&g_csr_src[e + 6]);
            int a7 = __ldg(&g_csr_src[e + 7]);
            uint4 v0 = __ldg(&ysv[(size_t)a0 * 8 + sl]);
            uint4 v1 = __ldg(&ysv[(size_t)a1 * 8 + sl]);
            uint4 v2 = __ldg(&ysv[(size_t)a2 * 8 + sl]);
            uint4 v3 = __ldg(&ysv[(size_t)a3 * 8 + sl]);
            uint4 v4 = __ldg(&ysv[(size_t)a4 * 8 + sl]);
            uint4 v5 = __ldg(&ysv[(size_t)a5 * 8 + sl]);
            uint4 v6 = __ldg(&ysv[(size_t)a6 * 8 + sl]);
            uint4 v7 = __ldg(&ysv[(size_t)a7 * 8 + sl]);
            add_h8(s0, v0); add_h8(s1, v1); add_h8(s2, v2); add_h8(s3, v3);
            add_h8(s0, v4); add_h8(s1, v5); add_h8(s2, v6); add_h8(s3, v7);
        }
        for (; e + 2 <= end; e += 2) {
            int a0 = __ldg(&g_csr_src[e]);
            int a1 = __ldg(&g_csr_src[e + 1]);
            uint4 v0 = __ldg(&ysv[(size_t)a0 * 8 + sl]);
            uint4 v1 = __ldg(&ysv[(size_t)a1 * 8 + sl]);
            add_h8(s0, v0); add_h8(s1, v1);
        }
        if (e < end) {
            int a0 = __ldg(&g_csr_src[e]);
            add_h8(s0, __ldg(&ysv[(size_t)a0 * 8 + sl]));
        }

        float4 b0 = *(const float4*)(bias + sl * 8);
        float4 b1 = *(const float4*)(bias + sl * 8 + 4);
        float bb[8] = {b0.x, b0.y, b0.z, b0.w, b1.x, b1.y, b1.z, b1.w};
#pragma unroll
        for (int i = 0; i < 8; i++) {
            float s = (s0[i] + s1[i]) + (s2[i] + s3[i]);
            h[i] = fmaxf(s * dvn + bb[i], 0.f);
        }
        float* hp = g_h + (size_t)node * HID + sl * 8;
        *(float4*)hp       = make_float4(h[0], h[1], h[2], h[3]);
        *(float4*)(hp + 4) = make_float4(h[4], h[5], h[6], h[7]);
    }

    if (doPool) {
        __shared__ float sh[32][64];
        __shared__ int sg[32];
        int nl = threadIdx.x >> 3;
        int sli = threadIdx.x & 7;
        *(float4*)&sh[nl][sli * 8]     = make_float4(h[0], h[1], h[2], h[3]);
        *(float4*)&sh[nl][sli * 8 + 4] = make_float4(h[4], h[5], h[6], h[7]);
        if (sli == 0) sg[nl] = valid ? __ldg(&batch[node]) : -1;
        __syncthreads();

        if (threadIdx.x < 64) {
            int gmin = 0x7fffffff, gmax = -1;
#pragma unroll
            for (int i = 0; i < 32; i++) {
                int g = sg[i];
                if (g >= 0) { gmin = min(gmin, g); gmax = max(gmax, g); }
            }
            for (int g = gmin; g <= gmax; g++) {
                float s = 0.f;
                int cnt = 0;
#pragma unroll
                for (int i = 0; i < 32; i++)
                    if (sg[i] == g) { s += sh[i][threadIdx.x]; cnt++; }
                atomicAdd(&g_pooled[g * JKDIM + off + threadIdx.x], s);
                if (doCount && threadIdx.x == 0) atomicAdd(&g_cnt[g], (float)cnt);
            }
        }
    }
}

// ---------------- head: mean-pool normalize + linear + log_softmax ----------
__global__ void head_kernel(const float* __restrict__ Wl,
                            const float* __restrict__ bl,
                            float* __restrict__ out) {
    int g = threadIdx.x;
    if (g >= NGRAPHS) return;
    float ic = 1.f / fmaxf(g_cnt[g], 1.f);
    float logit[10];
#pragma unroll
    for (int j = 0; j < 10; j++) logit[j] = bl[j];
    for (int k = 0; k < JKDIM; k++) {
        float v = g_pooled[g * JKDIM + k] * ic;
#pragma unroll
        for (int j = 0; j < 10; j++) logit[j] += v * Wl[k * 10 + j];
    }
    float m = logit[0];
#pragma unroll
    for (int j = 1; j < 10; j++) m = fmaxf(m, logit[j]);
    float s = 0.f;
#pragma unroll
    for (int j = 0; j < 10; j++) s += expf(logit[j] - m);
    float lse = logf(s);
#pragma unroll
    for (int j = 0; j < 10; j++) out[g * 10 + j] = logit[j] - m - lse;
}

// ---------------- launch -----------------------------------------------------
extern "C" void kernel_launch(void* const* d_in, const int* in_sizes, int n_in,
                              void* d_out, int out_size) {
    const float* x  = (const float*)d_in[0];
    const float* W1 = (const float*)d_in[1];
    const float* b1 = (const float*)d_in[2];
    const float* W2 = (const float*)d_in[3];
    const float* b2 = (const float*)d_in[4];
    const float* W3 = (const float*)d_in[5];
    const float* b3 = (const float*)d_in[6];
    const float* W4 = (const float*)d_in[7];
    const float* b4 = (const float*)d_in[8];
    const float* Wl = (const float*)d_in[9];
    const float* bl = (const float*)d_in[10];
    const int* ei    = (const int*)d_in[11];
    const int* batch = (const int*)d_in[12];
    float* out = (float*)d_out;

    int N = in_sizes[12];
    int E = in_sizes[11] / 2;

    int threads = 256;
    int gridN = (N + threads - 1) / threads;
    int gridE = (E + threads - 1) / threads;
    int gemmGrid = (N + 127) / 128;
    int aggGrid = (N * 8 + threads - 1) / threads;
    int nScanBlocks = (N + SCAN_BLK - 1) / SCAN_BLK;

    zero_kernel<<<gridN, threads>>>(N);
    degree_kernel<<<gridE, threads>>>(ei, E);
    block_scan_kernel<<<nScanBlocks, SCAN_BLK>>>(N);
    scan_blocksums_kernel<<<1, MAX_SCAN_BLOCKS>>>(nScanBlocks);
    apply_offsets_kernel<<<gridN, threads>>>(N, E);
    fill_kernel<<<gridE, threads>>>(ei, E);

    // layer 1 (input x, K=128); pool x1 -> [0:64), also counts
    gemm_kernel<128><<<gemmGrid, 256>>>(x, W1, N);
    aggregate_kernel<<<aggGrid, threads>>>(b1, batch, 0, 1, 1, N);

    // layer 2; pool x2 -> [64:128)
    gemm_kernel<64><<<gemmGrid, 256>>>(nullptr, W2, N);
    aggregate_kernel<<<aggGrid, threads>>>(b2, batch, 64, 1, 0, N);

    // layer 3 (no pool)
    gemm_kernel<64><<<gemmGrid, 256>>>(nullptr, W3, N);
    aggregate_kernel<<<aggGrid, threads>>>(b3, batch, 0, 0, 0, N);

    // layer 4 (overwrites x3, as in reference); pool -> [128:192)
    gemm_kernel<64><<<gemmGrid, 256>>>(nullptr, W4, N);
    aggregate_kernel<<<aggGrid, threads>>>(b4, batch, 128, 1, 0, N);

    head_kernel<<<1, 64>>>(Wl, bl, out);
}

// round 8
// speedup vs baseline: 1.0733x; 1.0569x over previous
#include <cuda_runtime.h>
#include <cuda_fp16.h>
#include <math.h>

#define NMAX 100000
#define EMAX 1600000
#define HID 64
#define NGRAPHS 64
#define JKDIM 192
#define SCAN_BLK 1024
#define MAX_SCAN_BLOCKS 128

// ---------------- scratch (device globals: no allocation allowed) ----------
__device__ int    g_deg[NMAX];
__device__ int    g_rowptr[NMAX + 1];
__device__ int    g_cursor[NMAX];
__device__ int    g_scanloc[NMAX];
__device__ int    g_blocksum[MAX_SCAN_BLOCKS];
__device__ int    g_blockoff[MAX_SCAN_BLOCKS];
__device__ int    g_csr_src[EMAX];
__device__ float  g_dinv[NMAX];
__device__ __half g_ysh[(size_t)NMAX * HID];  // dinv-scaled A@W, fp16
__device__ float  g_h [(size_t)NMAX * HID];
__device__ float  g_pooled[NGRAPHS * JKDIM];
__device__ float  g_cnt[NGRAPHS];

// ---------------- f32x2 helpers ---------------------------------------------
__device__ __forceinline__ unsigned long long pack2(float lo, float hi) {
    unsigned long long r;
    asm("mov.b64 %0, {%1, %2};" : "=l"(r) : "f"(lo), "f"(hi));
    return r;
}
__device__ __forceinline__ void unpack2(unsigned long long v, float& lo, float& hi) {
    asm("mov.b64 {%0, %1}, %2;" : "=f"(lo), "=f"(hi) : "l"(v));
}
__device__ __forceinline__ void fma2(unsigned long long& d, unsigned long long a,
                                     unsigned long long b) {
    asm("fma.rn.f32x2 %0, %1, %2, %0;" : "+l"(d) : "l"(a), "l"(b));
}

// ---------------- init ------------------------------------------------------
__global__ void zero_kernel(int N) {
    int i = blockIdx.x * blockDim.x + threadIdx.x;
    if (i < N) g_deg[i] = 0;
    if (i < NGRAPHS * JKDIM) g_pooled[i] = 0.f;
    if (i < NGRAPHS) g_cnt[i] = 0.f;
}

__global__ void degree_kernel(const int* __restrict__ ei, int E) {
    int e = blockIdx.x * blockDim.x + threadIdx.x;
    if (e < E) atomicAdd(&g_deg[ei[E + e]], 1);
}

// ---------------- scan (also computes dinv) ----------------------------------
__global__ __launch_bounds__(SCAN_BLK) void block_scan_kernel(int N) {
    __shared__ int bs[SCAN_BLK];
    int t = threadIdx.x;
    int i = blockIdx.x * SCAN_BLK + t;
    int v = (i < N) ? g_deg[i] : 0;
    if (i < N) g_dinv[i] = rsqrtf((float)(v + 1));  // +1 self loop
    bs[t] = v;
    __syncthreads();
#pragma unroll
    for (int off = 1; off < SCAN_BLK; off <<= 1) {
        int u = (t >= off) ? bs[t - off] : 0;
        __syncthreads();
        bs[t] += u;
        __syncthreads();
    }
    if (i < N) g_scanloc[i] = bs[t] - v;
    if (t == SCAN_BLK - 1) g_blocksum[blockIdx.x] = bs[t];
}

__global__ void scan_blocksums_kernel(int nb) {
    __shared__ int bs[MAX_SCAN_BLOCKS];
    int t = threadIdx.x;
    int v = (t < nb) ? g_blocksum[t] : 0;
    bs[t] = v;
    __syncthreads();
#pragma unroll
    for (int off = 1; off < MAX_SCAN_BLOCKS; off <<= 1) {
        int u = (t >= off) ? bs[t - off] : 0;
        __syncthreads();
        bs[t] += u;
        __syncthreads();
    }
    if (t < nb) g_blockoff[t] = bs[t] - v;
}

__global__ void apply_offsets_kernel(int N, int E) {
    int i = blockIdx.x * blockDim.x + threadIdx.x;
    if (i < N) {
        int r = g_scanloc[i] + g_blockoff[i / SCAN_BLK];
        g_rowptr[i] = r;
        g_cursor[i] = r;
    }
    if (i == 0) g_rowptr[N] = E;
}

__global__ void fill_kernel(const int* __restrict__ ei, int E) {
    int e = blockIdx.x * blockDim.x + threadIdx.x;
    if (e < E) {
        int d = ei[E + e];
        int pos = atomicAdd(&g_cursor[d], 1);
        g_csr_src[pos] = ei[e];
    }
}

// -------- GEMM: ysh = fp16((A @ W) * dinv[row]), f32x2 inner loop -----------
template <int KTOT>
__global__ __launch_bounds__(256) void gemm_kernel(const float* __restrict__ A,
                                                   const float* __restrict__ W,
                                                   int N) {
    __shared__ float Ask[32][132];
    __shared__ float Ws[32][64];

    const float* __restrict__ Ap = A ? A : g_h;

    int tid = threadIdx.x;
    int tx = tid & 15;
    int ty = tid >> 4;
    int rowBase = blockIdx.x * 128;

    unsigned long long acc2[4][4];
#pragma unroll
    for (int i = 0; i < 4; i++)
#pragma unroll
        for (int j = 0; j < 4; j++) acc2[i][j] = 0ULL;

    for (int kc = 0; kc < KTOT; kc += 32) {
        {
            int k8 = tid & 7;
            int r0 = tid >> 3;
#pragma unroll
            for (int p = 0; p < 4; p++) {
                int r = r0 + p * 32;
                int grow = rowBase + r;
                float4 v = make_float4(0.f, 0.f, 0.f, 0.f);
                if (grow < N)
                    v = *(const float4*)(Ap + (size_t)grow * KTOT + kc + k8 * 4);
                Ask[k8 * 4 + 0][r] = v.x;
                Ask[k8 * 4 + 1][r] = v.y;
                Ask[k8 * 4 + 2][r] = v.z;
                Ask[k8 * 4 + 3][r] = v.w;
            }
        }
        {
            int c4 = tid & 15;
            int kr = tid >> 4;
#pragma unroll
            for (int p = 0; p < 2; p++) {
                int k = kr + p * 16;
                *(float4*)&Ws[k][c4 * 4] =
                    *(const float4*)(W + (size_t)(kc + k) * 64 + c4 * 4);
            }
        }
        __syncthreads();
#pragma unroll
        for (int kk = 0; kk < 32; kk++) {
            float4 w = *(const float4*)&Ws[kk][tx * 4];
            float4 a0 = *(const float4*)&Ask[kk][ty * 8];
            float4 a1 = *(const float4*)&Ask[kk][ty * 8 + 4];

            unsigned long long w2[4];
            w2[0] = pack2(w.x, w.x);
            w2[1] = pack2(w.y, w.y);
            w2[2] = pack2(w.z, w.z);
            w2[3] = pack2(w.w, w.w);

            unsigned long long a2[4];
            a2[0] = pack2(a0.x, a0.y);
            a2[1] = pack2(a0.z, a0.w);
            a2[2] = pack2(a1.x, a1.y);
            a2[3] = pack2(a1.z, a1.w);

#pragma unroll
            for (int i = 0; i < 4; i++)
#pragma unroll
                for (int j = 0; j < 4; j++) fma2(acc2[i][j], a2[i], w2[j]);
        }
        __syncthreads();
    }

#pragma unroll
    for (int i2 = 0; i2 < 4; i2++) {
#pragma unroll
        for (int sub = 0; sub < 2; sub++) {
            int row = rowBase + ty * 8 + i2 * 2 + sub;
            if (row < N) {
                float dv = g_dinv[row];
                float lo, hi;
                float4 v;
                unpack2(acc2[i2][0], lo, hi); v.x = (sub ? hi : lo) * dv;
                unpack2(acc2[i2][1], lo, hi); v.y = (sub ? hi : lo) * dv;
                unpack2(acc2[i2][2], lo, hi); v.z = (sub ? hi : lo) * dv;
                unpack2(acc2[i2][3], lo, hi); v.w = (sub ? hi : lo) * dv;
                __half2 p0 = __floats2half2_rn(v.x, v.y);
                __half2 p1 = __floats2half2_rn(v.z, v.w);
                uint2 st;
                st.x = *(unsigned int*)&p0;
                st.y = *(unsigned int*)&p1;
                *(uint2*)(g_ysh + (size_t)row * HID + tx * 4) = st;
            }
        }
    }
}

// ---- aggregation: 16 thr/node (R4 layout), fp16 gather, 8-deep unroll ------
// h[n] = relu(dinv[n]*(ysh[n] + sum ysh[src]) + b)
__device__ __forceinline__ void add_h4(float* acc, uint2 v) {
    __half2 h0 = *(__half2*)&v.x;
    __half2 h1 = *(__half2*)&v.y;
    float2 f0 = __half22float2(h0);
    float2 f1 = __half22float2(h1);
    acc[0] += f0.x; acc[1] += f0.y;
    acc[2] += f1.x; acc[3] += f1.y;
}

__global__ __launch_bounds__(256) void aggregate_kernel(
    const float* __restrict__ bias, const int* __restrict__ batch,
    int off, int doPool, int doCount, int N) {
    int gid = blockIdx.x * blockDim.x + threadIdx.x;
    int node = gid >> 4;
    int sl = gid & 15;            // 4 halves (8 bytes) per thread
    bool valid = node < N;

    const uint2* __restrict__ ysv = (const uint2*)g_ysh;  // 16 uint2 per row

    float h[4] = {0.f, 0.f, 0.f, 0.f};

    if (valid) {
        int beg = __ldg(&g_rowptr[node]);
        int end = __ldg(&g_rowptr[node + 1]);
        float dvn = __ldg(&g_dinv[node]);

        float s0[4] = {0.f, 0.f, 0.f, 0.f};
        float s1[4] = {0.f, 0.f, 0.f, 0.f};
        float s2[4] = {0.f, 0.f, 0.f, 0.f};
        float s3[4] = {0.f, 0.f, 0.f, 0.f};
        add_h4(s0, __ldg(&ysv[(size_t)node * 16 + sl]));  // self loop

        int e = beg;
        for (; e + 8 <= end; e += 8) {
            int a0 = __ldg(&g_csr_src[e]);
            int a1 = __ldg(&g_csr_src[e + 1]);
            int a2 = __ldg(&g_csr_src[e + 2]);
            int a3 = __ldg(&g_csr_src[e + 3]);
            int a4 = __ldg(&g_csr_src[e + 4]);
            int a5 = __ldg(&g_csr_src[e + 5]);
            int a6 = __ldg(&g_csr_src[e + 6]);
            int a7 = __ldg(&g_csr_src[e + 7]);
            uint2 v0 = __ldg(&ysv[(size_t)a0 * 16 + sl]);
            uint2 v1 = __ldg(&ysv[(size_t)a1 * 16 + sl]);
            uint2 v2 = __ldg(&ysv[(size_t)a2 * 16 + sl]);
            uint2 v3 = __ldg(&ysv[(size_t)a3 * 16 + sl]);
            uint2 v4 = __ldg(&ysv[(size_t)a4 * 16 + sl]);
            uint2 v5 = __ldg(&ysv[(size_t)a5 * 16 + sl]);
            uint2 v6 = __ldg(&ysv[(size_t)a6 * 16 + sl]);
            uint2 v7 = __ldg(&ysv[(size_t)a7 * 16 + sl]);
            add_h4(s0, v0); add_h4(s1, v1); add_h4(s2, v2); add_h4(s3, v3);
            add_h4(s0, v4); add_h4(s1, v5); add_h4(s2, v6); add_h4(s3, v7);
        }
        for (; e + 2 <= end; e += 2) {
            int a0 = __ldg(&g_csr_src[e]);
            int a1 = __ldg(&g_csr_src[e + 1]);
            uint2 v0 = __ldg(&ysv[(size_t)a0 * 16 + sl]);
            uint2 v1 = __ldg(&ysv[(size_t)a1 * 16 + sl]);
            add_h4(s0, v0); add_h4(s1, v1);
        }
        if (e < end) {
            int a0 = __ldg(&g_csr_src[e]);
            add_h4(s0, __ldg(&ysv[(size_t)a0 * 16 + sl]));
        }

        float4 b4 = *(const float4*)(bias + sl * 4);
        float bb[4] = {b4.x, b4.y, b4.z, b4.w};
#pragma unroll
        for (int i = 0; i < 4; i++) {
            float s = (s0[i] + s1[i]) + (s2[i] + s3[i]);
            h[i] = fmaxf(s * dvn + bb[i], 0.f);
        }
        *(float4*)(g_h + (size_t)node * HID + sl * 4) =
            make_float4(h[0], h[1], h[2], h[3]);
    }

    if (doPool) {
        __shared__ float sh[16][64];
        __shared__ int sg[16];
        int nl = threadIdx.x >> 4;
        int sli = threadIdx.x & 15;
        *(float4*)&sh[nl][sli * 4] = make_float4(h[0], h[1], h[2], h[3]);
        if (sli == 0) sg[nl] = valid ? __ldg(&batch[node]) : -1;
        __syncthreads();

        if (threadIdx.x < 64) {
            int gmin = 0x7fffffff, gmax = -1;
#pragma unroll
            for (int i = 0; i < 16; i++) {
                int g = sg[i];
                if (g >= 0) { gmin = min(gmin, g); gmax = max(gmax, g); }
            }
            for (int g = gmin; g <= gmax; g++) {
                float s = 0.f;
                int cnt = 0;
#pragma unroll
                for (int i = 0; i < 16; i++)
                    if (sg[i] == g) { s += sh[i][threadIdx.x]; cnt++; }
                atomicAdd(&g_pooled[g * JKDIM + off + threadIdx.x], s);
                if (doCount && threadIdx.x == 0) atomicAdd(&g_cnt[g], (float)cnt);
            }
        }
    }
}

// ---------------- head: mean-pool normalize + linear + log_softmax ----------
__global__ void head_kernel(const float* __restrict__ Wl,
                            const float* __restrict__ bl,
                            float* __restrict__ out) {
    int g = threadIdx.x;
    if (g >= NGRAPHS) return;
    float ic = 1.f / fmaxf(g_cnt[g], 1.f);
    float logit[10];
#pragma unroll
    for (int j = 0; j < 10; j++) logit[j] = bl[j];
    for (int k = 0; k < JKDIM; k++) {
        float v = g_pooled[g * JKDIM + k] * ic;
#pragma unroll
        for (int j = 0; j < 10; j++) logit[j] += v * Wl[k * 10 + j];
    }
    float m = logit[0];
#pragma unroll
    for (int j = 1; j < 10; j++) m = fmaxf(m, logit[j]);
    float s = 0.f;
#pragma unroll
    for (int j = 0; j < 10; j++) s += expf(logit[j] - m);
    float lse = logf(s);
#pragma unroll
    for (int j = 0; j < 10; j++) out[g * 10 + j] = logit[j] - m - lse;
}

// ---------------- launch -----------------------------------------------------
extern "C" void kernel_launch(void* const* d_in, const int* in_sizes, int n_in,
                              void* d_out, int out_size) {
    const float* x  = (const float*)d_in[0];
    const float* W1 = (const float*)d_in[1];
    const float* b1 = (const float*)d_in[2];
    const float* W2 = (const float*)d_in[3];
    const float* b2 = (const float*)d_in[4];
    const float* W3 = (const float*)d_in[5];
    const float* b3 = (const float*)d_in[6];
    const float* W4 = (const float*)d_in[7];
    const float* b4 = (const float*)d_in[8];
    const float* Wl = (const float*)d_in[9];
    const float* bl = (const float*)d_in[10];
    const int* ei    = (const int*)d_in[11];
    const int* batch = (const int*)d_in[12];
    float* out = (float*)d_out;

    int N = in_sizes[12];
    int E = in_sizes[11] / 2;

    int threads = 256;
    int gridN = (N + threads - 1) / threads;
    int gridE = (E + threads - 1) / threads;
    int gemmGrid = (N + 127) / 128;
    int aggGrid = (N * 16 + threads - 1) / threads;
    int nScanBlocks = (N + SCAN_BLK - 1) / SCAN_BLK;

    zero_kernel<<<gridN, threads>>>(N);
    degree_kernel<<<gridE, threads>>>(ei, E);
    block_scan_kernel<<<nScanBlocks, SCAN_BLK>>>(N);
    scan_blocksums_kernel<<<1, MAX_SCAN_BLOCKS>>>(nScanBlocks);
    apply_offsets_kernel<<<gridN, threads>>>(N, E);
    fill_kernel<<<gridE, threads>>>(ei, E);

    // layer 1 (input x, K=128); pool x1 -> [0:64), also counts
    gemm_kernel<128><<<gemmGrid, 256>>>(x, W1, N);
    aggregate_kernel<<<aggGrid, threads>>>(b1, batch, 0, 1, 1, N);

    // layer 2; pool x2 -> [64:128)
    gemm_kernel<64><<<gemmGrid, 256>>>(nullptr, W2, N);
    aggregate_kernel<<<aggGrid, threads>>>(b2, batch, 64, 1, 0, N);

    // layer 3 (no pool)
    gemm_kernel<64><<<gemmGrid, 256>>>(nullptr, W3, N);
    aggregate_kernel<<<aggGrid, threads>>>(b3, batch, 0, 0, 0, N);

    // layer 4 (overwrites x3, as in reference); pool -> [128:192)
    gemm_kernel<64><<<gemmGrid, 256>>>(nullptr, W4, N);
    aggregate_kernel<<<aggGrid, threads>>>(b4, batch, 128, 1, 0, N);

    head_kernel<<<1, 64>>>(Wl, bl, out);
}

// round 9
// speedup vs baseline: 1.2811x; 1.1936x over previous
#include <cuda_runtime.h>
#include <cuda_fp16.h>
#include <math.h>

#define NMAX 100000
#define EMAX 1600000
#define HID 64
#define NGRAPHS 64
#define JKDIM 192
#define SCAN_BLK 1024
#define MAX_SCAN_BLOCKS 128

// ---------------- scratch (device globals: no allocation allowed) ----------
__device__ int    g_deg[NMAX];
__device__ int    g_rowptr[NMAX + 1];
__device__ int    g_cursor[NMAX];
__device__ int    g_scanloc[NMAX];
__device__ int    g_blocksum[MAX_SCAN_BLOCKS];
__device__ int    g_blockoff[MAX_SCAN_BLOCKS];
__device__ int    g_csr_src[EMAX];
__device__ float  g_dinv[NMAX];
__device__ __half g_ysh[(size_t)NMAX * HID];  // dinv-scaled A@W, fp16
__device__ __half g_hh [(size_t)NMAX * HID];  // layer activations, fp16
__device__ float  g_pooled[NGRAPHS * JKDIM];
__device__ float  g_cnt[NGRAPHS];

__device__ __forceinline__ unsigned int h2bits(__half2 h) {
    return *(unsigned int*)&h;
}
__device__ __forceinline__ unsigned int smem_u32(const void* p) {
    unsigned int a;
    asm("{ .reg .u64 t; cvta.to.shared.u64 t, %1; cvt.u32.u64 %0, t; }"
        : "=r"(a) : "l"(p));
    return a;
}

// ---------------- init ------------------------------------------------------
__global__ void zero_kernel(int N) {
    int i = blockIdx.x * blockDim.x + threadIdx.x;
    if (i < N) g_deg[i] = 0;
    if (i < NGRAPHS * JKDIM) g_pooled[i] = 0.f;
    if (i < NGRAPHS) g_cnt[i] = 0.f;
}

__global__ void degree_kernel(const int* __restrict__ ei, int E) {
    int e = blockIdx.x * blockDim.x + threadIdx.x;
    if (e < E) atomicAdd(&g_deg[ei[E + e]], 1);
}

// ---------------- scan (also computes dinv) ----------------------------------
__global__ __launch_bounds__(SCAN_BLK) void block_scan_kernel(int N) {
    __shared__ int bs[SCAN_BLK];
    int t = threadIdx.x;
    int i = blockIdx.x * SCAN_BLK + t;
    int v = (i < N) ? g_deg[i] : 0;
    if (i < N) g_dinv[i] = rsqrtf((float)(v + 1));  // +1 self loop
    bs[t] = v;
    __syncthreads();
#pragma unroll
    for (int off = 1; off < SCAN_BLK; off <<= 1) {
        int u = (t >= off) ? bs[t - off] : 0;
        __syncthreads();
        bs[t] += u;
        __syncthreads();
    }
    if (i < N) g_scanloc[i] = bs[t] - v;
    if (t == SCAN_BLK - 1) g_blocksum[blockIdx.x] = bs[t];
}

__global__ void scan_blocksums_kernel(int nb) {
    __shared__ int bs[MAX_SCAN_BLOCKS];
    int t = threadIdx.x;
    int v = (t < nb) ? g_blocksum[t] : 0;
    bs[t] = v;
    __syncthreads();
#pragma unroll
    for (int off = 1; off < MAX_SCAN_BLOCKS; off <<= 1) {
        int u = (t >= off) ? bs[t - off] : 0;
        __syncthreads();
        bs[t] += u;
        __syncthreads();
    }
    if (t < nb) g_blockoff[t] = bs[t] - v;
}

__global__ void apply_offsets_kernel(int N, int E) {
    int i = blockIdx.x * blockDim.x + threadIdx.x;
    if (i < N) {
        int r = g_scanloc[i] + g_blockoff[i / SCAN_BLK];
        g_rowptr[i] = r;
        g_cursor[i] = r;
    }
    if (i == 0) g_rowptr[N] = E;
}

__global__ void fill_kernel(const int* __restrict__ ei, int E) {
    int e = blockIdx.x * blockDim.x + threadIdx.x;
    if (e < E) {
        int d = ei[E + e];
        int pos = atomicAdd(&g_cursor[d], 1);
        g_csr_src[pos] = ei[e];
    }
}

// -------- HMMA GEMM: ysh = fp16((A @ W) * dinv[row]) ------------------------
// Tile 128x64, 8 warps; warp w computes rows [w*16, w*16+16) x all 64 cols.
// A staged in smem fp16 (converted from fp32 if FP16IN==false); W fp32->fp16.
template <int KTOT, bool FP16IN>
__global__ __launch_bounds__(256) void gemm_hmma(const float* __restrict__ Af,
                                                 const float* __restrict__ W,
                                                 int N) {
    __shared__ __half As[128][40];   // stride 40 halves (80B): conflict-free
    __shared__ __half Bs[32][72];    // stride 72 halves (144B): conflict-free

    int tid = threadIdx.x;
    int warp = tid >> 5;
    int lane = tid & 31;
    int rowBase = blockIdx.x * 128;
    int wrow = warp * 16;

    float acc[8][4];
#pragma unroll
    for (int i = 0; i < 8; i++)
#pragma unroll
        for (int j = 0; j < 4; j++) acc[i][j] = 0.f;

    for (int kc = 0; kc < KTOT; kc += 32) {
        // ---- stage A chunk: 128 rows x 32 k (fp16) ----
        {
            int ar = tid >> 1;
            int ak = (tid & 1) * 16;
            int grow = rowBase + ar;
            uint4 u0 = make_uint4(0, 0, 0, 0);
            uint4 u1 = make_uint4(0, 0, 0, 0);
            if (FP16IN) {
                if (grow < N) {
                    const uint4* p = (const uint4*)(g_hh + (size_t)grow * KTOT + kc + ak);
                    u0 = p[0];
                    u1 = p[1];
                }
            } else {
                if (grow < N) {
                    const float4* p = (const float4*)(Af + (size_t)grow * KTOT + kc + ak);
                    float4 f0 = p[0], f1 = p[1], f2 = p[2], f3 = p[3];
                    u0.x = h2bits(__floats2half2_rn(f0.x, f0.y));
                    u0.y = h2bits(__floats2half2_rn(f0.z, f0.w));
                    u0.z = h2bits(__floats2half2_rn(f1.x, f1.y));
                    u0.w = h2bits(__floats2half2_rn(f1.z, f1.w));
                    u1.x = h2bits(__floats2half2_rn(f2.x, f2.y));
                    u1.y = h2bits(__floats2half2_rn(f2.z, f2.w));
                    u1.z = h2bits(__floats2half2_rn(f3.x, f3.y));
                    u1.w = h2bits(__floats2half2_rn(f3.z, f3.w));
                }
            }
            *(uint4*)&As[ar][ak] = u0;
            *(uint4*)&As[ar][ak + 8] = u1;
        }
        // ---- stage B chunk: 32 k x 64 n (fp16) ----
        {
            int br = tid >> 3;
            int bc = (tid & 7) * 8;
            const float4* p = (const float4*)(W + (size_t)(kc + br) * 64 + bc);
            float4 w0 = p[0], w1 = p[1];
            uint4 u;
            u.x = h2bits(__floats2half2_rn(w0.x, w0.y));
            u.y = h2bits(__floats2half2_rn(w0.z, w0.w));
            u.z = h2bits(__floats2half2_rn(w1.x, w1.y));
            u.w = h2bits(__floats2half2_rn(w1.z, w1.w));
            *(uint4*)&Bs[br][bc] = u;
        }
        __syncthreads();

#pragma unroll
        for (int c = 0; c < 2; c++) {   // two k16 sub-chunks
            unsigned int a0, a1, a2, a3;
            unsigned int aaddr =
                smem_u32(&As[wrow + (lane & 15)][c * 16 + (lane >> 4) * 8]);
            asm volatile(
                "ldmatrix.sync.aligned.m8n8.x4.shared.b16 {%0,%1,%2,%3}, [%4];"
                : "=r"(a0), "=r"(a1), "=r"(a2), "=r"(a3) : "r"(aaddr));

#pragma unroll
            for (int nb = 0; nb < 8; nb += 2) {
                unsigned int b0, b1, b2, b3;
                unsigned int baddr =
                    smem_u32(&Bs[c * 16 + (lane & 15)][nb * 8 + (lane >> 4) * 8]);
                asm volatile(
                    "ldmatrix.sync.aligned.m8n8.x4.trans.shared.b16 {%0,%1,%2,%3}, [%4];"
                    : "=r"(b0), "=r"(b1), "=r"(b2), "=r"(b3) : "r"(baddr));
                asm volatile(
                    "mma.sync.aligned.m16n8k16.row.col.f32.f16.f16.f32 "
                    "{%0,%1,%2,%3}, {%4,%5,%6,%7}, {%8,%9}, {%0,%1,%2,%3};"
                    : "+f"(acc[nb][0]), "+f"(acc[nb][1]),
                      "+f"(acc[nb][2]), "+f"(acc[nb][3])
                    : "r"(a0), "r"(a1), "r"(a2), "r"(a3), "r"(b0), "r"(b1));
                asm volatile(
                    "mma.sync.aligned.m16n8k16.row.col.f32.f16.f16.f32 "
                    "{%0,%1,%2,%3}, {%4,%5,%6,%7}, {%8,%9}, {%0,%1,%2,%3};"
                    : "+f"(acc[nb + 1][0]), "+f"(acc[nb + 1][1]),
                      "+f"(acc[nb + 1][2]), "+f"(acc[nb + 1][3])
                    : "r"(a0), "r"(a1), "r"(a2), "r"(a3), "r"(b2), "r"(b3));
            }
        }
        __syncthreads();
    }

    // ---- epilogue: scale by dinv, convert fp16, store ----
    int gID = lane >> 2;   // 0-7
    int tID = lane & 3;
    int r0 = rowBase + wrow + gID;
    int r1 = r0 + 8;
    float dv0 = (r0 < N) ? g_dinv[r0] : 0.f;
    float dv1 = (r1 < N) ? g_dinv[r1] : 0.f;
#pragma unroll
    for (int nb = 0; nb < 8; nb++) {
        int col = nb * 8 + tID * 2;
        if (r0 < N) {
            __half2 p = __floats2half2_rn(acc[nb][0] * dv0, acc[nb][1] * dv0);
            *(__half2*)(g_ysh + (size_t)r0 * HID + col) = p;
        }
        if (r1 < N) {
            __half2 p = __floats2half2_rn(acc[nb][2] * dv1, acc[nb][3] * dv1);
            *(__half2*)(g_ysh + (size_t)r1 * HID + col) = p;
        }
    }
}

// ---- aggregation: 16 thr/node, fp16 gather, 8-deep unroll + fused pooling ---
// h[n] = relu(dinv[n]*(ysh[n] + sum ysh[src]) + b); stores h as fp16 to g_hh.
__device__ __forceinline__ void add_h4(float* acc, uint2 v) {
    __half2 h0 = *(__half2*)&v.x;
    __half2 h1 = *(__half2*)&v.y;
    float2 f0 = __half22float2(h0);
    float2 f1 = __half22float2(h1);
    acc[0] += f0.x; acc[1] += f0.y;
    acc[2] += f1.x; acc[3] += f1.y;
}

__global__ __launch_bounds__(256) void aggregate_kernel(
    const float* __restrict__ bias, const int* __restrict__ batch,
    int off, int doPool, int doCount, int N) {
    int gid = blockIdx.x * blockDim.x + threadIdx.x;
    int node = gid >> 4;
    int sl = gid & 15;            // 4 halves (8 bytes) per thread
    bool valid = node < N;

    const uint2* __restrict__ ysv = (const uint2*)g_ysh;  // 16 uint2 per row

    float h[4] = {0.f, 0.f, 0.f, 0.f};

    if (valid) {
        int beg = __ldg(&g_rowptr[node]);
        int end = __ldg(&g_rowptr[node + 1]);
        float dvn = __ldg(&g_dinv[node]);

        float s0[4] = {0.f, 0.f, 0.f, 0.f};
        float s1[4] = {0.f, 0.f, 0.f, 0.f};
        float s2[4] = {0.f, 0.f, 0.f, 0.f};
        float s3[4] = {0.f, 0.f, 0.f, 0.f};
        add_h4(s0, __ldg(&ysv[(size_t)node * 16 + sl]));  // self loop

        int e = beg;
        for (; e + 8 <= end; e += 8) {
            int a0 = __ldg(&g_csr_src[e]);
            int a1 = __ldg(&g_csr_src[e + 1]);
            int a2 = __ldg(&g_csr_src[e + 2]);
            int a3 = __ldg(&g_csr_src[e + 3]);
            int a4 = __ldg(&g_csr_src[e + 4]);
            int a5 = __ldg(&g_csr_src[e + 5]);
            int a6 = __ldg(&g_csr_src[e + 6]);
            int a7 = __ldg(&g_csr_src[e + 7]);
            uint2 v0 = __ldg(&ysv[(size_t)a0 * 16 + sl]);
            uint2 v1 = __ldg(&ysv[(size_t)a1 * 16 + sl]);
            uint2 v2 = __ldg(&ysv[(size_t)a2 * 16 + sl]);
            uint2 v3 = __ldg(&ysv[(size_t)a3 * 16 + sl]);
            uint2 v4 = __ldg(&ysv[(size_t)a4 * 16 + sl]);
            uint2 v5 = __ldg(&ysv[(size_t)a5 * 16 + sl]);
            uint2 v6 = __ldg(&ysv[(size_t)a6 * 16 + sl]);
            uint2 v7 = __ldg(&ysv[(size_t)a7 * 16 + sl]);
            add_h4(s0, v0); add_h4(s1, v1); add_h4(s2, v2); add_h4(s3, v3);
            add_h4(s0, v4); add_h4(s1, v5); add_h4(s2, v6); add_h4(s3, v7);
        }
        for (; e + 2 <= end; e += 2) {
            int a0 = __ldg(&g_csr_src[e]);
            int a1 = __ldg(&g_csr_src[e + 1]);
            uint2 v0 = __ldg(&ysv[(size_t)a0 * 16 + sl]);
            uint2 v1 = __ldg(&ysv[(size_t)a1 * 16 + sl]);
            add_h4(s0, v0); add_h4(s1, v1);
        }
        if (e < end) {
            int a0 = __ldg(&g_csr_src[e]);
            add_h4(s0, __ldg(&ysv[(size_t)a0 * 16 + sl]));
        }

        float4 b4 = *(const float4*)(bias + sl * 4);
        float bb[4] = {b4.x, b4.y, b4.z, b4.w};
#pragma unroll
        for (int i = 0; i < 4; i++) {
            float s = (s0[i] + s1[i]) + (s2[i] + s3[i]);
            h[i] = fmaxf(s * dvn + bb[i], 0.f);
        }
        uint2 st;
        st.x = h2bits(__floats2half2_rn(h[0], h[1]));
        st.y = h2bits(__floats2half2_rn(h[2], h[3]));
        *(uint2*)(g_hh + (size_t)node * HID + sl * 4) = st;
    }

    if (doPool) {
        __shared__ float sh[16][64];
        __shared__ int sg[16];
        int nl = threadIdx.x >> 4;
        int sli = threadIdx.x & 15;
        *(float4*)&sh[nl][sli * 4] = make_float4(h[0], h[1], h[2], h[3]);
        if (sli == 0) sg[nl] = valid ? __ldg(&batch[node]) : -1;
        __syncthreads();

        if (threadIdx.x < 64) {
            int gmin = 0x7fffffff, gmax = -1;
#pragma unroll
            for (int i = 0; i < 16; i++) {
                int g = sg[i];
                if (g >= 0) { gmin = min(gmin, g); gmax = max(gmax, g); }
            }
            for (int g = gmin; g <= gmax; g++) {
                float s = 0.f;
                int cnt = 0;
#pragma unroll
                for (int i = 0; i < 16; i++)
                    if (sg[i] == g) { s += sh[i][threadIdx.x]; cnt++; }
                atomicAdd(&g_pooled[g * JKDIM + off + threadIdx.x], s);
                if (doCount && threadIdx.x == 0) atomicAdd(&g_cnt[g], (float)cnt);
            }
        }
    }
}

// ---------------- head: mean-pool normalize + linear + log_softmax ----------
__global__ void head_kernel(const float* __restrict__ Wl,
                            const float* __restrict__ bl,
                            float* __restrict__ out) {
    int g = threadIdx.x;
    if (g >= NGRAPHS) return;
    float ic = 1.f / fmaxf(g_cnt[g], 1.f);
    float logit[10];
#pragma unroll
    for (int j = 0; j < 10; j++) logit[j] = bl[j];
    for (int k = 0; k < JKDIM; k++) {
        float v = g_pooled[g * JKDIM + k] * ic;
#pragma unroll
        for (int j = 0; j < 10; j++) logit[j] += v * Wl[k * 10 + j];
    }
    float m = logit[0];
#pragma unroll
    for (int j = 1; j < 10; j++) m = fmaxf(m, logit[j]);
    float s = 0.f;
#pragma unroll
    for (int j = 0; j < 10; j++) s += expf(logit[j] - m);
    float lse = logf(s);
#pragma unroll
    for (int j = 0; j < 10; j++) out[g * 10 + j] = logit[j] - m - lse;
}

// ---------------- launch -----------------------------------------------------
extern "C" void kernel_launch(void* const* d_in, const int* in_sizes, int n_in,
                              void* d_out, int out_size) {
    const float* x  = (const float*)d_in[0];
    const float* W1 = (const float*)d_in[1];
    const float* b1 = (const float*)d_in[2];
    const float* W2 = (const float*)d_in[3];
    const float* b2 = (const float*)d_in[4];
    const float* W3 = (const float*)d_in[5];
    const float* b3 = (const float*)d_in[6];
    const float* W4 = (const float*)d_in[7];
    const float* b4 = (const float*)d_in[8];
    const float* Wl = (const float*)d_in[9];
    const float* bl = (const float*)d_in[10];
    const int* ei    = (const int*)d_in[11];
    const int* batch = (const int*)d_in[12];
    float* out = (float*)d_out;

    int N = in_sizes[12];
    int E = in_sizes[11] / 2;

    int threads = 256;
    int gridN = (N + threads - 1) / threads;
    int gridE = (E + threads - 1) / threads;
    int gemmGrid = (N + 127) / 128;
    int aggGrid = (N * 16 + threads - 1) / threads;
    int nScanBlocks = (N + SCAN_BLK - 1) / SCAN_BLK;

    zero_kernel<<<gridN, threads>>>(N);
    degree_kernel<<<gridE, threads>>>(ei, E);
    block_scan_kernel<<<nScanBlocks, SCAN_BLK>>>(N);
    scan_blocksums_kernel<<<1, MAX_SCAN_BLOCKS>>>(nScanBlocks);
    apply_offsets_kernel<<<gridN, threads>>>(N, E);
    fill_kernel<<<gridE, threads>>>(ei, E);

    // layer 1 (input x fp32, K=128); pool x1 -> [0:64), also counts
    gemm_hmma<128, false><<<gemmGrid, 256>>>(x, W1, N);
    aggregate_kernel<<<aggGrid, threads>>>(b1, batch, 0, 1, 1, N);

    // layer 2 (fp16 in); pool x2 -> [64:128)
    gemm_hmma<64, true><<<gemmGrid, 256>>>(nullptr, W2, N);
    aggregate_kernel<<<aggGrid, threads>>>(b2, batch, 64, 1, 0, N);

    // layer 3 (no pool)
    gemm_hmma<64, true><<<gemmGrid, 256>>>(nullptr, W3, N);
    aggregate_kernel<<<aggGrid, threads>>>(b3, batch, 0, 0, 0, N);

    // layer 4 (overwrites x3, as in reference); pool -> [128:192)
    gemm_hmma<64, true><<<gemmGrid, 256>>>(nullptr, W4, N);
    aggregate_kernel<<<aggGrid, threads>>>(b4, batch, 128, 1, 0, N);

    head_kernel<<<1, 64>>>(Wl, bl, out);
}

// round 10
// speedup vs baseline: 1.3874x; 1.0829x over previous
#include <cuda_runtime.h>
#include <cuda_fp16.h>
#include <math.h>

#define NMAX 100000
#define EMAX 1600000
#define HID 64
#define NGRAPHS 64
#define JKDIM 192
#define SCAN_BLK 1024
#define MAX_SCAN_BLOCKS 128

// ---------------- scratch (device globals: no allocation allowed) ----------
__device__ int    g_deg[NMAX];
__device__ int    g_rowptr[NMAX + 1];
__device__ int    g_cursor[NMAX];
__device__ int    g_scanloc[NMAX];
__device__ int    g_blocksum[MAX_SCAN_BLOCKS];
__device__ int    g_blockoff[MAX_SCAN_BLOCKS];
__device__ int    g_csr_src[EMAX];
__device__ float  g_dinv[NMAX];
__device__ __half g_ysh[(size_t)NMAX * HID];  // dinv-scaled A@W, fp16
__device__ __half g_hh [(size_t)NMAX * HID];  // layer activations, fp16
__device__ float  g_pooled[NGRAPHS * JKDIM];
__device__ float  g_cnt[NGRAPHS];

__device__ __forceinline__ unsigned int h2bits(__half2 h) {
    return *(unsigned int*)&h;
}
__device__ __forceinline__ unsigned int smem_u32(const void* p) {
    unsigned int a;
    asm("{ .reg .u64 t; cvta.to.shared.u64 t, %1; cvt.u32.u64 %0, t; }"
        : "=r"(a) : "l"(p));
    return a;
}

// ---------------- init ------------------------------------------------------
__global__ void zero_kernel(int N) {
    int i = blockIdx.x * blockDim.x + threadIdx.x;
    if (i < N) g_deg[i] = 0;
    if (i < NGRAPHS * JKDIM) g_pooled[i] = 0.f;
    if (i < NGRAPHS) g_cnt[i] = 0.f;
}

__global__ void degree_kernel(const int* __restrict__ ei, int E) {
    int e = blockIdx.x * blockDim.x + threadIdx.x;
    if (e < E) atomicAdd(&g_deg[ei[E + e]], 1);
}

// ---------------- scan (also computes dinv) ----------------------------------
__global__ __launch_bounds__(SCAN_BLK) void block_scan_kernel(int N) {
    __shared__ int bs[SCAN_BLK];
    int t = threadIdx.x;
    int i = blockIdx.x * SCAN_BLK + t;
    int v = (i < N) ? g_deg[i] : 0;
    if (i < N) g_dinv[i] = rsqrtf((float)(v + 1));  // +1 self loop
    bs[t] = v;
    __syncthreads();
#pragma unroll
    for (int off = 1; off < SCAN_BLK; off <<= 1) {
        int u = (t >= off) ? bs[t - off] : 0;
        __syncthreads();
        bs[t] += u;
        __syncthreads();
    }
    if (i < N) g_scanloc[i] = bs[t] - v;
    if (t == SCAN_BLK - 1) g_blocksum[blockIdx.x] = bs[t];
}

__global__ void scan_blocksums_kernel(int nb) {
    __shared__ int bs[MAX_SCAN_BLOCKS];
    int t = threadIdx.x;
    int v = (t < nb) ? g_blocksum[t] : 0;
    bs[t] = v;
    __syncthreads();
#pragma unroll
    for (int off = 1; off < MAX_SCAN_BLOCKS; off <<= 1) {
        int u = (t >= off) ? bs[t - off] : 0;
        __syncthreads();
        bs[t] += u;
        __syncthreads();
    }
    if (t < nb) g_blockoff[t] = bs[t] - v;
}

__global__ void apply_offsets_kernel(int N, int E) {
    int i = blockIdx.x * blockDim.x + threadIdx.x;
    if (i < N) {
        int r = g_scanloc[i] + g_blockoff[i / SCAN_BLK];
        g_rowptr[i] = r;
        g_cursor[i] = r;
    }
    if (i == 0) g_rowptr[N] = E;
}

__global__ void fill_kernel(const int* __restrict__ ei, int E) {
    int e = blockIdx.x * blockDim.x + threadIdx.x;
    if (e < E) {
        int d = ei[E + e];
        int pos = atomicAdd(&g_cursor[d], 1);
        g_csr_src[pos] = ei[e];
    }
}

// -------- HMMA GEMM: ysh = fp16((A @ W) * dinv[row]) ------------------------
template <int KTOT, bool FP16IN>
__global__ __launch_bounds__(256) void gemm_hmma(const float* __restrict__ Af,
                                                 const float* __restrict__ W,
                                                 int N) {
    __shared__ __half As[128][40];
    __shared__ __half Bs[32][72];

    int tid = threadIdx.x;
    int warp = tid >> 5;
    int lane = tid & 31;
    int rowBase = blockIdx.x * 128;
    int wrow = warp * 16;

    float acc[8][4];
#pragma unroll
    for (int i = 0; i < 8; i++)
#pragma unroll
        for (int j = 0; j < 4; j++) acc[i][j] = 0.f;

    for (int kc = 0; kc < KTOT; kc += 32) {
        {
            int ar = tid >> 1;
            int ak = (tid & 1) * 16;
            int grow = rowBase + ar;
            uint4 u0 = make_uint4(0, 0, 0, 0);
            uint4 u1 = make_uint4(0, 0, 0, 0);
            if (FP16IN) {
                if (grow < N) {
                    const uint4* p = (const uint4*)(g_hh + (size_t)grow * KTOT + kc + ak);
                    u0 = p[0];
                    u1 = p[1];
                }
            } else {
                if (grow < N) {
                    const float4* p = (const float4*)(Af + (size_t)grow * KTOT + kc + ak);
                    float4 f0 = p[0], f1 = p[1], f2 = p[2], f3 = p[3];
                    u0.x = h2bits(__floats2half2_rn(f0.x, f0.y));
                    u0.y = h2bits(__floats2half2_rn(f0.z, f0.w));
                    u0.z = h2bits(__floats2half2_rn(f1.x, f1.y));
                    u0.w = h2bits(__floats2half2_rn(f1.z, f1.w));
                    u1.x = h2bits(__floats2half2_rn(f2.x, f2.y));
                    u1.y = h2bits(__floats2half2_rn(f2.z, f2.w));
                    u1.z = h2bits(__floats2half2_rn(f3.x, f3.y));
                    u1.w = h2bits(__floats2half2_rn(f3.z, f3.w));
                }
            }
            *(uint4*)&As[ar][ak] = u0;
            *(uint4*)&As[ar][ak + 8] = u1;
        }
        {
            int br = tid >> 3;
            int bc = (tid & 7) * 8;
            const float4* p = (const float4*)(W + (size_t)(kc + br) * 64 + bc);
            float4 w0 = p[0], w1 = p[1];
            uint4 u;
            u.x = h2bits(__floats2half2_rn(w0.x, w0.y));
            u.y = h2bits(__floats2half2_rn(w0.z, w0.w));
            u.z = h2bits(__floats2half2_rn(w1.x, w1.y));
            u.w = h2bits(__floats2half2_rn(w1.z, w1.w));
            *(uint4*)&Bs[br][bc] = u;
        }
        __syncthreads();

#pragma unroll
        for (int c = 0; c < 2; c++) {
            unsigned int a0, a1, a2, a3;
            unsigned int aaddr =
                smem_u32(&As[wrow + (lane & 15)][c * 16 + (lane >> 4) * 8]);
            asm volatile(
                "ldmatrix.sync.aligned.m8n8.x4.shared.b16 {%0,%1,%2,%3}, [%4];"
                : "=r"(a0), "=r"(a1), "=r"(a2), "=r"(a3) : "r"(aaddr));

#pragma unroll
            for (int nb = 0; nb < 8; nb += 2) {
                unsigned int b0, b1, b2, b3;
                unsigned int baddr =
                    smem_u32(&Bs[c * 16 + (lane & 15)][nb * 8 + (lane >> 4) * 8]);
                asm volatile(
                    "ldmatrix.sync.aligned.m8n8.x4.trans.shared.b16 {%0,%1,%2,%3}, [%4];"
                    : "=r"(b0), "=r"(b1), "=r"(b2), "=r"(b3) : "r"(baddr));
                asm volatile(
                    "mma.sync.aligned.m16n8k16.row.col.f32.f16.f16.f32 "
                    "{%0,%1,%2,%3}, {%4,%5,%6,%7}, {%8,%9}, {%0,%1,%2,%3};"
                    : "+f"(acc[nb][0]), "+f"(acc[nb][1]),
                      "+f"(acc[nb][2]), "+f"(acc[nb][3])
                    : "r"(a0), "r"(a1), "r"(a2), "r"(a3), "r"(b0), "r"(b1));
                asm volatile(
                    "mma.sync.aligned.m16n8k16.row.col.f32.f16.f16.f32 "
                    "{%0,%1,%2,%3}, {%4,%5,%6,%7}, {%8,%9}, {%0,%1,%2,%3};"
                    : "+f"(acc[nb + 1][0]), "+f"(acc[nb + 1][1]),
                      "+f"(acc[nb + 1][2]), "+f"(acc[nb + 1][3])
                    : "r"(a0), "r"(a1), "r"(a2), "r"(a3), "r"(b2), "r"(b3));
            }
        }
        __syncthreads();
    }

    int gID = lane >> 2;
    int tID = lane & 3;
    int r0 = rowBase + wrow + gID;
    int r1 = r0 + 8;
    float dv0 = (r0 < N) ? g_dinv[r0] : 0.f;
    float dv1 = (r1 < N) ? g_dinv[r1] : 0.f;
#pragma unroll
    for (int nb = 0; nb < 8; nb++) {
        int col = nb * 8 + tID * 2;
        if (r0 < N) {
            __half2 p = __floats2half2_rn(acc[nb][0] * dv0, acc[nb][1] * dv0);
            *(__half2*)(g_ysh + (size_t)r0 * HID + col) = p;
        }
        if (r1 < N) {
            __half2 p = __floats2half2_rn(acc[nb][2] * dv1, acc[nb][3] * dv1);
            *(__half2*)(g_ysh + (size_t)r1 * HID + col) = p;
        }
    }
}

// ---- aggregation: 16 thr/node, fp16 gather, 4-deep unroll (low regs) --------
// h[n] = relu(dinv[n]*(ysh[n] + sum ysh[src]) + b)
__device__ __forceinline__ void add_h4(float* acc, uint2 v) {
    __half2 h0 = *(__half2*)&v.x;
    __half2 h1 = *(__half2*)&v.y;
    float2 f0 = __half22float2(h0);
    float2 f1 = __half22float2(h1);
    acc[0] += f0.x; acc[1] += f0.y;
    acc[2] += f1.x; acc[3] += f1.y;
}

__global__ __launch_bounds__(256) void aggregate_kernel(
    const float* __restrict__ bias, const int* __restrict__ batch,
    int off, int doPool, int doCount, int writeH, int N) {
    int gid = blockIdx.x * blockDim.x + threadIdx.x;
    int node = gid >> 4;
    int sl = gid & 15;            // 4 halves (8 bytes) per thread
    bool valid = node < N;

    const uint2* __restrict__ ysv = (const uint2*)g_ysh;  // 16 uint2 per row

    float h[4] = {0.f, 0.f, 0.f, 0.f};

    if (valid) {
        int beg = __ldg(&g_rowptr[node]);
        int end = __ldg(&g_rowptr[node + 1]);
        float dvn = __ldg(&g_dinv[node]);

        float s0[4] = {0.f, 0.f, 0.f, 0.f};
        float s1[4] = {0.f, 0.f, 0.f, 0.f};
        add_h4(s0, __ldg(&ysv[(size_t)node * 16 + sl]));  // self loop

        int e = beg;
        for (; e + 4 <= end; e += 4) {
            int a0 = __ldg(&g_csr_src[e]);
            int a1 = __ldg(&g_csr_src[e + 1]);
            int a2 = __ldg(&g_csr_src[e + 2]);
            int a3 = __ldg(&g_csr_src[e + 3]);
            uint2 v0 = __ldg(&ysv[(size_t)a0 * 16 + sl]);
            uint2 v1 = __ldg(&ysv[(size_t)a1 * 16 + sl]);
            uint2 v2 = __ldg(&ysv[(size_t)a2 * 16 + sl]);
            uint2 v3 = __ldg(&ysv[(size_t)a3 * 16 + sl]);
            add_h4(s0, v0); add_h4(s1, v1);
            add_h4(s0, v2); add_h4(s1, v3);
        }
        for (; e < end; e++) {
            int a0 = __ldg(&g_csr_src[e]);
            add_h4(s0, __ldg(&ysv[(size_t)a0 * 16 + sl]));
        }

        float4 b4 = *(const float4*)(bias + sl * 4);
        float bb[4] = {b4.x, b4.y, b4.z, b4.w};
#pragma unroll
        for (int i = 0; i < 4; i++)
            h[i] = fmaxf((s0[i] + s1[i]) * dvn + bb[i], 0.f);

        if (writeH) {
            uint2 st;
            st.x = h2bits(__floats2half2_rn(h[0], h[1]));
            st.y = h2bits(__floats2half2_rn(h[2], h[3]));
            *(uint2*)(g_hh + (size_t)node * HID + sl * 4) = st;
        }
    }

    if (doPool) {
        __shared__ float sh[16][64];
        __shared__ int sg[16];
        int nl = threadIdx.x >> 4;
        int sli = threadIdx.x & 15;
        *(float4*)&sh[nl][sli * 4] = make_float4(h[0], h[1], h[2], h[3]);
        if (sli == 0) sg[nl] = valid ? __ldg(&batch[node]) : -1;
        __syncthreads();

        if (threadIdx.x < 64) {
            int gmin = 0x7fffffff, gmax = -1;
#pragma unroll
            for (int i = 0; i < 16; i++) {
                int g = sg[i];
                if (g >= 0) { gmin = min(gmin, g); gmax = max(gmax, g); }
            }
            for (int g = gmin; g <= gmax; g++) {
                float s = 0.f;
                int cnt = 0;
#pragma unroll
                for (int i = 0; i < 16; i++)
                    if (sg[i] == g) { s += sh[i][threadIdx.x]; cnt++; }
                atomicAdd(&g_pooled[g * JKDIM + off + threadIdx.x], s);
                if (doCount && threadIdx.x == 0) atomicAdd(&g_cnt[g], (float)cnt);
            }
        }
    }
}

// ---------------- head: mean-pool normalize + linear + log_softmax ----------
__global__ void head_kernel(const float* __restrict__ Wl,
                            const float* __restrict__ bl,
                            float* __restrict__ out) {
    int g = threadIdx.x;
    if (g >= NGRAPHS) return;
    float ic = 1.f / fmaxf(g_cnt[g], 1.f);
    float logit[10];
#pragma unroll
    for (int j = 0; j < 10; j++) logit[j] = bl[j];
    for (int k = 0; k < JKDIM; k++) {
        float v = g_pooled[g * JKDIM + k] * ic;
#pragma unroll
        for (int j = 0; j < 10; j++) logit[j] += v * Wl[k * 10 + j];
    }
    float m = logit[0];
#pragma unroll
    for (int j = 1; j < 10; j++) m = fmaxf(m, logit[j]);
    float s = 0.f;
#pragma unroll
    for (int j = 0; j < 10; j++) s += expf(logit[j] - m);
    float lse = logf(s);
#pragma unroll
    for (int j = 0; j < 10; j++) out[g * 10 + j] = logit[j] - m - lse;
}

// ---------------- launch -----------------------------------------------------
extern "C" void kernel_launch(void* const* d_in, const int* in_sizes, int n_in,
                              void* d_out, int out_size) {
    const float* x  = (const float*)d_in[0];
    const float* W1 = (const float*)d_in[1];
    const float* b1 = (const float*)d_in[2];
    const float* W2 = (const float*)d_in[3];
    const float* b2 = (const float*)d_in[4];
    const float* W3 = (const float*)d_in[5];
    const float* b3 = (const float*)d_in[6];
    const float* W4 = (const float*)d_in[7];
    const float* b4 = (const float*)d_in[8];
    const float* Wl = (const float*)d_in[9];
    const float* bl = (const float*)d_in[10];
    const int* ei    = (const int*)d_in[11];
    const int* batch = (const int*)d_in[12];
    float* out = (float*)d_out;

    int N = in_sizes[12];
    int E = in_sizes[11] / 2;

    int threads = 256;
    int gridN = (N + threads - 1) / threads;
    int gridE = (E + threads - 1) / threads;
    int gemmGrid = (N + 127) / 128;
    int aggGrid = (N * 16 + threads - 1) / threads;
    int nScanBlocks = (N + SCAN_BLK - 1) / SCAN_BLK;

    // one-time host-side stream/event resources (no device memory involved)
    static cudaStream_t s2 = nullptr;
    static cudaEvent_t evFork = nullptr, evJoin = nullptr;
    if (!s2) {
        cudaStreamCreateWithFlags(&s2, cudaStreamNonBlocking);
        cudaEventCreateWithFlags(&evFork, cudaEventDisableTiming);
        cudaEventCreateWithFlags(&evJoin, cudaEventDisableTiming);
    }

    zero_kernel<<<gridN, threads>>>(N);
    degree_kernel<<<gridE, threads>>>(ei, E);
    block_scan_kernel<<<nScanBlocks, SCAN_BLK>>>(N);   // dinv ready after this

    // fork: gemm1 (needs only x, W1, dinv) overlaps rest of CSR build
    cudaEventRecord(evFork, 0);
    cudaStreamWaitEvent(s2, evFork, 0);
    gemm_hmma<128, false><<<gemmGrid, 256, 0, s2>>>(x, W1, N);
    cudaEventRecord(evJoin, s2);

    scan_blocksums_kernel<<<1, MAX_SCAN_BLOCKS>>>(nScanBlocks);
    apply_offsets_kernel<<<gridN, threads>>>(N, E);
    fill_kernel<<<gridE, threads>>>(ei, E);

    cudaStreamWaitEvent(0, evJoin, 0);

    // layer 1; pool x1 -> [0:64), counts
    aggregate_kernel<<<aggGrid, threads>>>(b1, batch, 0, 1, 1, 1, N);

    // layer 2; pool x2 -> [64:128)
    gemm_hmma<64, true><<<gemmGrid, 256>>>(nullptr, W2, N);
    aggregate_kernel<<<aggGrid, threads>>>(b2, batch, 64, 1, 0, 1, N);

    // layer 3 (no pool)
    gemm_hmma<64, true><<<gemmGrid, 256>>>(nullptr, W3, N);
    aggregate_kernel<<<aggGrid, threads>>>(b3, batch, 0, 0, 0, 1, N);

    // layer 4 (overwrites x3); pool -> [128:192); h never read again
    gemm_hmma<64, true><<<gemmGrid, 256>>>(nullptr, W4, N);
    aggregate_kernel<<<aggGrid, threads>>>(b4, batch, 128, 1, 0, 0, N);

    head_kernel<<<1, 64>>>(Wl, bl, out);
}